// round 6
// baseline (speedup 1.0000x reference)
#include <cuda_runtime.h>
#include <cstdint>

// Problem constants: x (1,64,256,256), W (192,64), bias (192), 8x8 windows of 32x32.
#define NWIN 64
#define TOK  1024
#define C    64
#define WELEMS (TOK*C)          // 65536 floats per window per tensor

// Scratch (device globals — no allocation allowed)
__device__ float g_q [NWIN*WELEMS];
__device__ float g_k [NWIN*WELEMS];
__device__ float g_v [NWIN*WELEMS];
__device__ float g_qm[NWIN*WELEMS];
__device__ float g_km[NWIN*WELEMS];
__device__ float g_qr[NWIN*C];
__device__ float g_kr[NWIN*C];
__device__ float g_ar[NWIN*NWIN];

// ---------------------------------------------------------------------------
// tf32 helpers
// ---------------------------------------------------------------------------
__device__ __forceinline__ uint32_t f2tf32(float f) {
    uint32_t r;
    asm("cvt.rna.tf32.f32 %0, %1;" : "=r"(r) : "f"(f));
    return r;
}
// split f into hi (tf32) + lo (tf32 of residual)
__device__ __forceinline__ void split_tf32(float f, uint32_t& hi, uint32_t& lo) {
    hi = f2tf32(f);
    lo = f2tf32(f - __uint_as_float(hi));
}

#define MMA_TF32(d, a, b)                                                     \
    asm volatile(                                                             \
        "mma.sync.aligned.m16n8k8.row.col.f32.tf32.tf32.f32 "                 \
        "{%0,%1,%2,%3}, {%4,%5,%6,%7}, {%8,%9}, {%0,%1,%2,%3};"               \
        : "+f"((d)[0]), "+f"((d)[1]), "+f"((d)[2]), "+f"((d)[3])              \
        : "r"((a)[0]), "r"((a)[1]), "r"((a)[2]), "r"((a)[3]),                 \
          "r"((b)[0]), "r"((b)[1]))

// ---------------------------------------------------------------------------
// Kernel 1: qkv = gather(x) @ W^T + bias, split-tf32 (~fp32 accurate).
// grid (512, 2): x = token-tile of 128, y = half of the 192 outputs (96).
// 8 warps (4m x 2n), warp tile 32 x 48.
// smem: Xh/Xl[128][68], Wh/Wl[64][104] ([k][j]), bias[96]; stage [128][100].
// ---------------------------------------------------------------------------
#define QKV_XS 68
#define QKV_WS 104
#define QKV_SG 100
#define QKV_SMEM ((2*128*QKV_XS + 2*64*QKV_WS + 96)*4)   // 123264 B

__global__ __launch_bounds__(256) void qkv_kernel(const float* __restrict__ x,
                                                  const float* __restrict__ W,
                                                  const float* __restrict__ bias)
{
    extern __shared__ float sm[];
    uint32_t* Xh = (uint32_t*)sm;                       // [128][68]
    uint32_t* Xl = Xh + 128*QKV_XS;                     // [128][68]
    uint32_t* Wh = Xl + 128*QKV_XS;                     // [64][104]
    uint32_t* Wl = Wh + 64*QKV_WS;                      // [64][104]
    float*    bs = (float*)(Wl + 64*QKV_WS);            // [96]
    float*    Sg = sm;                                  // stage [128][100] (union)

    const int tt  = blockIdx.x;
    const int jh  = blockIdx.y;            // 0/1 -> output cols jh*96..+96
    const int w   = tt >> 3, seg = tt & 7;
    const int wy  = w >> 3,  wx  = w & 7;
    const int t0  = seg * 128;
    const int tid = threadIdx.x;
    const int warp = tid >> 5, lane = tid & 31;
    const int gid  = lane >> 2, tig = lane & 3;
    const int mwarp = warp >> 1;           // 0..3 -> 32 rows
    const int nwarp = warp & 1;            // 0..1 -> 48 cols

    // X: hi/lo tf32, [t][c]
    #pragma unroll
    for (int i = 0; i < 32; i++) {
        int idx = tid + i*256;
        int ch = idx >> 7, tl = idx & 127;
        int t  = t0 + tl;
        float v = x[ch*65536 + (wy*32 + (t>>5))*256 + wx*32 + (t&31)];
        uint32_t hi, lo; split_tf32(v, hi, lo);
        Xh[tl*QKV_XS + ch] = hi;
        Xl[tl*QKV_XS + ch] = lo;
    }
    // W: hi/lo tf32, [k][j_local]
    #pragma unroll
    for (int i = 0; i < 24; i++) {
        int idx = tid + i*256;             // 6144 = 96*64
        int ch = idx & 63, jl = idx >> 6;
        float v = W[(jh*96 + jl)*64 + ch];
        uint32_t hi, lo; split_tf32(v, hi, lo);
        Wh[ch*QKV_WS + jl] = hi;
        Wl[ch*QKV_WS + jl] = lo;
    }
    if (tid < 96) bs[tid] = bias[jh*96 + tid];
    __syncthreads();

    float acc[2][6][4];
    #pragma unroll
    for (int mt = 0; mt < 2; mt++)
        #pragma unroll
        for (int nt = 0; nt < 6; nt++)
            #pragma unroll
            for (int e = 0; e < 4; e++) acc[mt][nt][e] = 0.f;

    #pragma unroll
    for (int k0 = 0; k0 < 64; k0 += 8) {
        uint32_t ah[2][4], al[2][4];
        #pragma unroll
        for (int mt = 0; mt < 2; mt++) {
            int r = mwarp*32 + mt*16 + gid;
            ah[mt][0] = Xh[ r     *QKV_XS + k0 + tig];
            ah[mt][1] = Xh[(r + 8)*QKV_XS + k0 + tig];
            ah[mt][2] = Xh[ r     *QKV_XS + k0 + 4 + tig];
            ah[mt][3] = Xh[(r + 8)*QKV_XS + k0 + 4 + tig];
            al[mt][0] = Xl[ r     *QKV_XS + k0 + tig];
            al[mt][1] = Xl[(r + 8)*QKV_XS + k0 + tig];
            al[mt][2] = Xl[ r     *QKV_XS + k0 + 4 + tig];
            al[mt][3] = Xl[(r + 8)*QKV_XS + k0 + 4 + tig];
        }
        #pragma unroll
        for (int nt = 0; nt < 6; nt++) {
            int j = nwarp*48 + nt*8 + gid;
            uint32_t bh[2], bl[2];
            bh[0] = Wh[(k0     + tig)*QKV_WS + j];
            bh[1] = Wh[(k0 + 4 + tig)*QKV_WS + j];
            bl[0] = Wl[(k0     + tig)*QKV_WS + j];
            bl[1] = Wl[(k0 + 4 + tig)*QKV_WS + j];
            MMA_TF32(acc[0][nt], ah[0], bh);
            MMA_TF32(acc[0][nt], al[0], bh);
            MMA_TF32(acc[0][nt], ah[0], bl);
            MMA_TF32(acc[1][nt], ah[1], bh);
            MMA_TF32(acc[1][nt], al[1], bh);
            MMA_TF32(acc[1][nt], ah[1], bl);
        }
    }
    __syncthreads();   // operands dead; stage region reuses them (bias survives)

    #pragma unroll
    for (int mt = 0; mt < 2; mt++) {
        int r = mwarp*32 + mt*16 + gid;
        #pragma unroll
        for (int nt = 0; nt < 6; nt++) {
            int j = nwarp*48 + nt*8 + 2*tig;
            Sg[ r     *QKV_SG + j    ] = acc[mt][nt][0] + bs[j];
            Sg[ r     *QKV_SG + j + 1] = acc[mt][nt][1] + bs[j+1];
            Sg[(r + 8)*QKV_SG + j    ] = acc[mt][nt][2] + bs[j];
            Sg[(r + 8)*QKV_SG + j + 1] = acc[mt][nt][3] + bs[j+1];
        }
    }
    __syncthreads();

    // copy-out: 128 rows x 24 float4 (96 cols)
    #pragma unroll
    for (int p = 0; p < 12; p++) {
        int idx = tid + p*256;
        int t  = idx / 24, f4 = idx % 24;
        float4 v = *(float4*)&Sg[t*QKV_SG + f4*4];
        int jg = jh*96 + f4*4;
        float* dst = (jg < 64) ? g_q : (jg < 128) ? g_k : g_v;
        int jj = jg & 63;
        *(float4*)&dst[w*WELEMS + (t0 + t)*64 + jj] = v;
    }
}

// ---------------------------------------------------------------------------
// Kernel 2: q_r / k_r = mean over tokens.  grid (64, 2), 256 thr, float4.
// ---------------------------------------------------------------------------
__global__ void mean_kernel()
{
    __shared__ float4 red4[256];
    const int w   = blockIdx.x;
    const float* src = blockIdx.y ? g_k : g_q;
    float*       dst = blockIdx.y ? g_kr : g_qr;
    const int tid = threadIdx.x;
    const int l16 = tid & 15, g = tid >> 4;
    const float* base = src + w*WELEMS + l16*4;
    float4 acc = make_float4(0,0,0,0);
    #pragma unroll 4
    for (int t = g; t < 1024; t += 16) {
        float4 v = *(const float4*)&base[t*64];
        acc.x += v.x; acc.y += v.y; acc.z += v.z; acc.w += v.w;
    }
    red4[tid] = acc;
    __syncthreads();
    if (tid < 16) {
        float4 s = make_float4(0,0,0,0);
        #pragma unroll
        for (int gg = 0; gg < 16; gg++) {
            float4 v = red4[gg*16 + tid];
            s.x += v.x; s.y += v.y; s.z += v.z; s.w += v.w;
        }
        s.x *= (1.f/1024.f); s.y *= (1.f/1024.f);
        s.z *= (1.f/1024.f); s.w *= (1.f/1024.f);
        *(float4*)&dst[w*64 + tid*4] = s;
    }
}

// ---------------------------------------------------------------------------
// Kernel 3: a_r = relu(q_r @ k_r^T)   (64x64x64 — trivial, fp32)
// ---------------------------------------------------------------------------
__global__ void ar_kernel()
{
    __shared__ float qs[NWIN*C], ks[NWIN*C];
    const int tid = threadIdx.x;
    for (int i = tid; i < NWIN*C; i += 256) { qs[i] = g_qr[i]; ks[i] = g_kr[i]; }
    __syncthreads();
    for (int e = tid; e < NWIN*NWIN; e += 256) {
        int i = e >> 6, j = e & 63;
        float s = 0.f;
        #pragma unroll
        for (int c = 0; c < 64; c++) s += qs[i*64 + c] * ks[j*64 + c];
        g_ar[e] = fmaxf(s, 0.f);
    }
}

// ---------------------------------------------------------------------------
// Kernel 4: q_m/k_m = a_r @ src, split-tf32 GEMM (M=64, K=64, N=65536).
// grid (512, 2): 512 pos-tiles of 128. 8 warps (4m x 2n), warp tile 16x64.
// smem: Ah/Al[64][68], Bh/Bl[64][136]; stage [64][132]. 104 KB -> 2 CTAs/SM.
// ---------------------------------------------------------------------------
#define MIX_AS 68
#define MIX_BS 136
#define MIX_SG 132
#define MIX_SMEM ((2*64*MIX_AS + 2*64*MIX_BS)*4)   // 104448 B

__global__ __launch_bounds__(256) void mix_kernel()
{
    extern __shared__ float sm[];
    uint32_t* Ah = (uint32_t*)sm;            // [64][68]
    uint32_t* Al = Ah + 64*MIX_AS;           // [64][68]
    uint32_t* Bh = Al + 64*MIX_AS;           // [64][136]
    uint32_t* Bl = Bh + 64*MIX_BS;           // [64][136]
    float*    Sg = sm;                       // stage [64][132] (union)

    const int tid = threadIdx.x;
    const int warp = tid >> 5, lane = tid & 31;
    const int gid  = lane >> 2, tig = lane & 3;
    const int mwarp = warp >> 1;             // 0..3 -> 16 rows
    const int nwarp = warp & 1;              // 0..1 -> 64 cols
    const float* src = blockIdx.y ? g_k  : g_q;
    float*       dst = blockIdx.y ? g_km : g_qm;
    const int pos0 = blockIdx.x * 128;

    #pragma unroll
    for (int p = 0; p < 16; p++) {
        int e = tid + p*256;
        int i = e >> 6, j = e & 63;
        uint32_t hi, lo; split_tf32(g_ar[e], hi, lo);
        Ah[i*MIX_AS + j] = hi;
        Al[i*MIX_AS + j] = lo;
    }
    #pragma unroll
    for (int p = 0; p < 8; p++) {
        int idx = tid + p*256;               // 2048 float4
        int j = idx >> 5, f4 = idx & 31;
        float4 v = *(const float4*)&src[j*WELEMS + pos0 + f4*4];
        uint32_t* dh = &Bh[j*MIX_BS + f4*4];
        uint32_t* dl = &Bl[j*MIX_BS + f4*4];
        split_tf32(v.x, dh[0], dl[0]); split_tf32(v.y, dh[1], dl[1]);
        split_tf32(v.z, dh[2], dl[2]); split_tf32(v.w, dh[3], dl[3]);
    }
    __syncthreads();

    float acc[8][4];
    #pragma unroll
    for (int nt = 0; nt < 8; nt++)
        #pragma unroll
        for (int e = 0; e < 4; e++) acc[nt][e] = 0.f;

    #pragma unroll
    for (int k0 = 0; k0 < 64; k0 += 8) {
        uint32_t ah[4], al[4];
        int r = mwarp*16 + gid;
        ah[0] = Ah[ r     *MIX_AS + k0 + tig];
        ah[1] = Ah[(r + 8)*MIX_AS + k0 + tig];
        ah[2] = Ah[ r     *MIX_AS + k0 + 4 + tig];
        ah[3] = Ah[(r + 8)*MIX_AS + k0 + 4 + tig];
        al[0] = Al[ r     *MIX_AS + k0 + tig];
        al[1] = Al[(r + 8)*MIX_AS + k0 + tig];
        al[2] = Al[ r     *MIX_AS + k0 + 4 + tig];
        al[3] = Al[(r + 8)*MIX_AS + k0 + 4 + tig];
        #pragma unroll
        for (int nt = 0; nt < 8; nt++) {
            int n = nwarp*64 + nt*8 + gid;
            uint32_t bh[2], bl[2];
            bh[0] = Bh[(k0     + tig)*MIX_BS + n];
            bh[1] = Bh[(k0 + 4 + tig)*MIX_BS + n];
            bl[0] = Bl[(k0     + tig)*MIX_BS + n];
            bl[1] = Bl[(k0 + 4 + tig)*MIX_BS + n];
            MMA_TF32(acc[nt], ah, bh);
            MMA_TF32(acc[nt], al, bh);
            MMA_TF32(acc[nt], ah, bl);
        }
    }
    __syncthreads();

    {
        int r = mwarp*16 + gid;
        #pragma unroll
        for (int nt = 0; nt < 8; nt++) {
            int n = nwarp*64 + nt*8 + 2*tig;
            Sg[ r     *MIX_SG + n    ] = acc[nt][0];
            Sg[ r     *MIX_SG + n + 1] = acc[nt][1];
            Sg[(r + 8)*MIX_SG + n    ] = acc[nt][2];
            Sg[(r + 8)*MIX_SG + n + 1] = acc[nt][3];
        }
    }
    __syncthreads();

    #pragma unroll
    for (int p = 0; p < 8; p++) {
        int idx = tid + p*256;               // 2048 float4
        int i = idx >> 5, f4 = idx & 31;
        float4 v = *(float4*)&Sg[i*MIX_SG + f4*4];
        *(float4*)&dst[i*WELEMS + pos0 + f4*4] = v;
    }
}

// ---------------------------------------------------------------------------
// Kernel 5: per-window  O = relu(Qm @ Km^T) @ V via tf32 mma.sync.
// 64-row s-chunks -> smem 104 KB -> 2 CTAs/SM (co-resident CTAs hide the
// load/cvt/sync phases in each other's MMA phases). float4 gmem loads.
// ---------------------------------------------------------------------------
#define ATTN_SMEM ((128*68 + 64*68 + 64*68 + 128*68)*4)   // 104448 B

__global__ __launch_bounds__(256, 2) void attn_kernel(float* __restrict__ out)
{
    extern __shared__ float sm[];
    uint32_t* Qsu = (uint32_t*)sm;           // [128][68]
    uint32_t* Ksu = Qsu + 128*68;            // [64][68]
    uint32_t* Vsu = Ksu + 64*68;             // [64][68]
    uint32_t* Ssu = Vsu + 64*68;             // [128][68]
    float*    Ss  = (float*)Ssu;

    const int bx  = blockIdx.x;
    const int w   = bx >> 3, seg = bx & 7;
    const int wy  = w >> 3,  wx  = w & 7;
    const int t0  = seg * 128;
    const int tid = threadIdx.x;
    const int warp = tid >> 5, lane = tid & 31;
    const int gid  = lane >> 2, tig = lane & 3;
    const int mwarp = warp >> 1;             // 0..3 -> 32 rows
    const int nwarp = warp & 1;              // 0..1 -> 32 cols

    // Q tile (128x64) -> tf32 smem, float4 loads
    #pragma unroll
    for (int p = 0; p < 8; p++) {
        int fidx = tid + p*256;              // 2048 float4
        int tl = fidx >> 4, c4 = (fidx & 15)*4;
        float4 v = *(const float4*)&g_qm[w*WELEMS + (t0 + tl)*64 + c4];
        uint32_t* d = &Qsu[tl*68 + c4];
        d[0] = f2tf32(v.x); d[1] = f2tf32(v.y); d[2] = f2tf32(v.z); d[3] = f2tf32(v.w);
    }

    float oacc[2][4][4];
    #pragma unroll
    for (int mt = 0; mt < 2; mt++)
        #pragma unroll
        for (int nt = 0; nt < 4; nt++)
            #pragma unroll
            for (int e = 0; e < 4; e++) oacc[mt][nt][e] = 0.f;

    #pragma unroll 1
    for (int chunk = 0; chunk < 16; chunk++) {
        const int s0 = chunk * 64;
        __syncthreads();   // prev-iter readers of Ks/Vs/Ss done (chunk 0: Qs fence)

        // K chunk (64x64) + V chunk (64x64), float4
        #pragma unroll
        for (int p = 0; p < 4; p++) {
            int fidx = tid + p*256;          // 1024 float4
            int sl = fidx >> 4, c4 = (fidx & 15)*4;
            float4 v = *(const float4*)&g_km[w*WELEMS + (s0 + sl)*64 + c4];
            uint32_t* d = &Ksu[sl*68 + c4];
            d[0] = f2tf32(v.x); d[1] = f2tf32(v.y); d[2] = f2tf32(v.z); d[3] = f2tf32(v.w);
        }
        #pragma unroll
        for (int p = 0; p < 4; p++) {
            int fidx = tid + p*256;
            int sl = fidx >> 4, c4 = (fidx & 15)*4;
            float4 v = *(const float4*)&g_v[w*WELEMS + (s0 + sl)*64 + c4];
            uint32_t* d = &Vsu[sl*68 + c4];
            d[0] = f2tf32(v.x); d[1] = f2tf32(v.y); d[2] = f2tf32(v.z); d[3] = f2tf32(v.w);
        }
        __syncthreads();

        // ---- MMA1: S(128x64) = Q @ K^T, warp tile 32x32 ----
        float sacc[2][4][4];
        #pragma unroll
        for (int mt = 0; mt < 2; mt++)
            #pragma unroll
            for (int nt = 0; nt < 4; nt++)
                #pragma unroll
                for (int e = 0; e < 4; e++) sacc[mt][nt][e] = 0.f;

        #pragma unroll
        for (int k0 = 0; k0 < 64; k0 += 8) {
            uint32_t a[2][4];
            #pragma unroll
            for (int mt = 0; mt < 2; mt++) {
                int r = mwarp*32 + mt*16 + gid;
                a[mt][0] = Qsu[ r     *68 + k0 + tig];
                a[mt][1] = Qsu[(r + 8)*68 + k0 + tig];
                a[mt][2] = Qsu[ r     *68 + k0 + 4 + tig];
                a[mt][3] = Qsu[(r + 8)*68 + k0 + 4 + tig];
            }
            #pragma unroll
            for (int nt = 0; nt < 4; nt++) {
                int s = nwarp*32 + nt*8 + gid;
                uint32_t b[2];
                b[0] = Ksu[s*68 + k0 + tig];
                b[1] = Ksu[s*68 + k0 + 4 + tig];
                MMA_TF32(sacc[0][nt], a[0], b);
                MMA_TF32(sacc[1][nt], a[1], b);
            }
        }

        // relu + tf32 -> Ss[t][s]
        #pragma unroll
        for (int mt = 0; mt < 2; mt++) {
            int r = mwarp*32 + mt*16 + gid;
            #pragma unroll
            for (int nt = 0; nt < 4; nt++) {
                int cc = nwarp*32 + nt*8 + 2*tig;
                Ssu[ r     *68 + cc    ] = f2tf32(fmaxf(sacc[mt][nt][0], 0.f));
                Ssu[ r     *68 + cc + 1] = f2tf32(fmaxf(sacc[mt][nt][1], 0.f));
                Ssu[(r + 8)*68 + cc    ] = f2tf32(fmaxf(sacc[mt][nt][2], 0.f));
                Ssu[(r + 8)*68 + cc + 1] = f2tf32(fmaxf(sacc[mt][nt][3], 0.f));
            }
        }
        __syncthreads();

        // ---- MMA2: O(128x64) += S(128x64) @ V(64x64), warp tile 32x32 ----
        #pragma unroll
        for (int k0 = 0; k0 < 64; k0 += 8) {
            uint32_t a[2][4];
            #pragma unroll
            for (int mt = 0; mt < 2; mt++) {
                int r = mwarp*32 + mt*16 + gid;
                a[mt][0] = Ssu[ r     *68 + k0 + tig];
                a[mt][1] = Ssu[(r + 8)*68 + k0 + tig];
                a[mt][2] = Ssu[ r     *68 + k0 + 4 + tig];
                a[mt][3] = Ssu[(r + 8)*68 + k0 + 4 + tig];
            }
            #pragma unroll
            for (int nt = 0; nt < 4; nt++) {
                int c = nwarp*32 + nt*8 + gid;
                uint32_t b[2];
                b[0] = Vsu[(k0     + tig)*68 + c];
                b[1] = Vsu[(k0 + 4 + tig)*68 + c];
                MMA_TF32(oacc[0][nt], a[0], b);
                MMA_TF32(oacc[1][nt], a[1], b);
            }
        }
    }

    __syncthreads();
    // stage O [t][c] fp32, then coalesced NCHW-window stores
    #pragma unroll
    for (int mt = 0; mt < 2; mt++) {
        int r = mwarp*32 + mt*16 + gid;
        #pragma unroll
        for (int nt = 0; nt < 4; nt++) {
            int c = nwarp*32 + nt*8 + 2*tig;
            Ss[ r     *68 + c    ] = oacc[mt][nt][0];
            Ss[ r     *68 + c + 1] = oacc[mt][nt][1];
            Ss[(r + 8)*68 + c    ] = oacc[mt][nt][2];
            Ss[(r + 8)*68 + c + 1] = oacc[mt][nt][3];
        }
    }
    __syncthreads();

    #pragma unroll
    for (int i = 0; i < 32; i++) {
        int idx = tid + i*256;
        int ch = idx >> 7, tl = idx & 127;
        int t  = t0 + tl;
        out[ch*65536 + (wy*32 + (t>>5))*256 + wx*32 + (t&31)] = Ss[tl*68 + ch];
    }
}

// ---------------------------------------------------------------------------
extern "C" void kernel_launch(void* const* d_in, const int* in_sizes, int n_in,
                              void* d_out, int out_size)
{
    const float* x    = (const float*)d_in[0];
    const float* W    = (const float*)d_in[1];
    const float* bias = (const float*)d_in[2];
    float* out = (float*)d_out;

    cudaFuncSetAttribute(qkv_kernel,  cudaFuncAttributeMaxDynamicSharedMemorySize, QKV_SMEM);
    cudaFuncSetAttribute(mix_kernel,  cudaFuncAttributeMaxDynamicSharedMemorySize, MIX_SMEM);
    cudaFuncSetAttribute(attn_kernel, cudaFuncAttributeMaxDynamicSharedMemorySize, ATTN_SMEM);

    qkv_kernel <<<dim3(512, 2), 256, QKV_SMEM>>>(x, W, bias);
    mean_kernel<<<dim3(64, 2),  256>>>();
    ar_kernel  <<<1,            256>>>();
    mix_kernel <<<dim3(512, 2), 256, MIX_SMEM>>>();
    attn_kernel<<<512,          256, ATTN_SMEM>>>(out);
}

// round 8
// speedup vs baseline: 1.0638x; 1.0638x over previous
#include <cuda_runtime.h>
#include <cstdint>

// Problem constants: x (1,64,256,256), W (192,64), bias (192), 8x8 windows of 32x32.
#define NWIN 64
#define TOK  1024
#define C    64
#define WELEMS (TOK*C)          // 65536 floats per window per tensor

// Scratch (device globals — no allocation allowed)
__device__ float g_q [NWIN*WELEMS];
__device__ float g_k [NWIN*WELEMS];
__device__ float g_v [NWIN*WELEMS];
__device__ float g_qm[NWIN*WELEMS];
__device__ float g_km[NWIN*WELEMS];
__device__ float g_qr[NWIN*C];
__device__ float g_kr[NWIN*C];
__device__ float g_ar[NWIN*NWIN];

// ---------------------------------------------------------------------------
// tf32 helpers
// ---------------------------------------------------------------------------
__device__ __forceinline__ uint32_t f2tf32(float f) {
    uint32_t r;
    asm("cvt.rna.tf32.f32 %0, %1;" : "=r"(r) : "f"(f));
    return r;
}
__device__ __forceinline__ void split_tf32(float f, uint32_t& hi, uint32_t& lo) {
    hi = f2tf32(f);
    lo = f2tf32(f - __uint_as_float(hi));
}

#define MMA_TF32(d, a, b)                                                     \
    asm volatile(                                                             \
        "mma.sync.aligned.m16n8k8.row.col.f32.tf32.tf32.f32 "                 \
        "{%0,%1,%2,%3}, {%4,%5,%6,%7}, {%8,%9}, {%0,%1,%2,%3};"               \
        : "+f"((d)[0]), "+f"((d)[1]), "+f"((d)[2]), "+f"((d)[3])              \
        : "r"((a)[0]), "r"((a)[1]), "r"((a)[2]), "r"((a)[3]),                 \
          "r"((b)[0]), "r"((b)[1]))

// ---------------------------------------------------------------------------
// Kernel 1: qkv = gather(x) @ W^T + bias, split-tf32 (~fp32 accurate).
// grid (512, 2): x = token-tile of 128, y = half of the 192 outputs (96).
// ---------------------------------------------------------------------------
#define QKV_XS 68
#define QKV_WS 104
#define QKV_SG 100
#define QKV_SMEM ((2*128*QKV_XS + 2*64*QKV_WS + 96)*4)   // 123264 B

__global__ __launch_bounds__(256) void qkv_kernel(const float* __restrict__ x,
                                                  const float* __restrict__ W,
                                                  const float* __restrict__ bias)
{
    extern __shared__ float sm[];
    uint32_t* Xh = (uint32_t*)sm;                       // [128][68]
    uint32_t* Xl = Xh + 128*QKV_XS;                     // [128][68]
    uint32_t* Wh = Xl + 128*QKV_XS;                     // [64][104]
    uint32_t* Wl = Wh + 64*QKV_WS;                      // [64][104]
    float*    bs = (float*)(Wl + 64*QKV_WS);            // [96]
    float*    Sg = sm;                                  // stage [128][100] (union)

    const int tt  = blockIdx.x;
    const int jh  = blockIdx.y;
    const int w   = tt >> 3, seg = tt & 7;
    const int wy  = w >> 3,  wx  = w & 7;
    const int t0  = seg * 128;
    const int tid = threadIdx.x;
    const int warp = tid >> 5, lane = tid & 31;
    const int gid  = lane >> 2, tig = lane & 3;
    const int mwarp = warp >> 1;
    const int nwarp = warp & 1;

    #pragma unroll
    for (int i = 0; i < 32; i++) {
        int idx = tid + i*256;
        int ch = idx >> 7, tl = idx & 127;
        int t  = t0 + tl;
        float v = x[ch*65536 + (wy*32 + (t>>5))*256 + wx*32 + (t&31)];
        uint32_t hi, lo; split_tf32(v, hi, lo);
        Xh[tl*QKV_XS + ch] = hi;
        Xl[tl*QKV_XS + ch] = lo;
    }
    #pragma unroll
    for (int i = 0; i < 24; i++) {
        int idx = tid + i*256;
        int ch = idx & 63, jl = idx >> 6;
        float v = W[(jh*96 + jl)*64 + ch];
        uint32_t hi, lo; split_tf32(v, hi, lo);
        Wh[ch*QKV_WS + jl] = hi;
        Wl[ch*QKV_WS + jl] = lo;
    }
    if (tid < 96) bs[tid] = bias[jh*96 + tid];
    __syncthreads();

    float acc[2][6][4];
    #pragma unroll
    for (int mt = 0; mt < 2; mt++)
        #pragma unroll
        for (int nt = 0; nt < 6; nt++)
            #pragma unroll
            for (int e = 0; e < 4; e++) acc[mt][nt][e] = 0.f;

    #pragma unroll
    for (int k0 = 0; k0 < 64; k0 += 8) {
        uint32_t ah[2][4], al[2][4];
        #pragma unroll
        for (int mt = 0; mt < 2; mt++) {
            int r = mwarp*32 + mt*16 + gid;
            ah[mt][0] = Xh[ r     *QKV_XS + k0 + tig];
            ah[mt][1] = Xh[(r + 8)*QKV_XS + k0 + tig];
            ah[mt][2] = Xh[ r     *QKV_XS + k0 + 4 + tig];
            ah[mt][3] = Xh[(r + 8)*QKV_XS + k0 + 4 + tig];
            al[mt][0] = Xl[ r     *QKV_XS + k0 + tig];
            al[mt][1] = Xl[(r + 8)*QKV_XS + k0 + tig];
            al[mt][2] = Xl[ r     *QKV_XS + k0 + 4 + tig];
            al[mt][3] = Xl[(r + 8)*QKV_XS + k0 + 4 + tig];
        }
        #pragma unroll
        for (int nt = 0; nt < 6; nt++) {
            int j = nwarp*48 + nt*8 + gid;
            uint32_t bh[2], bl[2];
            bh[0] = Wh[(k0     + tig)*QKV_WS + j];
            bh[1] = Wh[(k0 + 4 + tig)*QKV_WS + j];
            bl[0] = Wl[(k0     + tig)*QKV_WS + j];
            bl[1] = Wl[(k0 + 4 + tig)*QKV_WS + j];
            MMA_TF32(acc[0][nt], ah[0], bh);
            MMA_TF32(acc[0][nt], al[0], bh);
            MMA_TF32(acc[0][nt], ah[0], bl);
            MMA_TF32(acc[1][nt], ah[1], bh);
            MMA_TF32(acc[1][nt], al[1], bh);
            MMA_TF32(acc[1][nt], ah[1], bl);
        }
    }
    __syncthreads();

    #pragma unroll
    for (int mt = 0; mt < 2; mt++) {
        int r = mwarp*32 + mt*16 + gid;
        #pragma unroll
        for (int nt = 0; nt < 6; nt++) {
            int j = nwarp*48 + nt*8 + 2*tig;
            Sg[ r     *QKV_SG + j    ] = acc[mt][nt][0] + bs[j];
            Sg[ r     *QKV_SG + j + 1] = acc[mt][nt][1] + bs[j+1];
            Sg[(r + 8)*QKV_SG + j    ] = acc[mt][nt][2] + bs[j];
            Sg[(r + 8)*QKV_SG + j + 1] = acc[mt][nt][3] + bs[j+1];
        }
    }
    __syncthreads();

    #pragma unroll
    for (int p = 0; p < 12; p++) {
        int idx = tid + p*256;
        int t  = idx / 24, f4 = idx % 24;
        float4 v = *(float4*)&Sg[t*QKV_SG + f4*4];
        int jg = jh*96 + f4*4;
        float* dst = (jg < 64) ? g_q : (jg < 128) ? g_k : g_v;
        int jj = jg & 63;
        *(float4*)&dst[w*WELEMS + (t0 + t)*64 + jj] = v;
    }
}

// ---------------------------------------------------------------------------
// Kernel 2: q_r / k_r = mean over tokens.  grid (64, 2), 256 thr, float4.
// ---------------------------------------------------------------------------
__global__ void mean_kernel()
{
    __shared__ float4 red4[256];
    const int w   = blockIdx.x;
    const float* src = blockIdx.y ? g_k : g_q;
    float*       dst = blockIdx.y ? g_kr : g_qr;
    const int tid = threadIdx.x;
    const int l16 = tid & 15, g = tid >> 4;
    const float* base = src + w*WELEMS + l16*4;
    float4 acc = make_float4(0,0,0,0);
    #pragma unroll 4
    for (int t = g; t < 1024; t += 16) {
        float4 v = *(const float4*)&base[t*64];
        acc.x += v.x; acc.y += v.y; acc.z += v.z; acc.w += v.w;
    }
    red4[tid] = acc;
    __syncthreads();
    if (tid < 16) {
        float4 s = make_float4(0,0,0,0);
        #pragma unroll
        for (int gg = 0; gg < 16; gg++) {
            float4 v = red4[gg*16 + tid];
            s.x += v.x; s.y += v.y; s.z += v.z; s.w += v.w;
        }
        s.x *= (1.f/1024.f); s.y *= (1.f/1024.f);
        s.z *= (1.f/1024.f); s.w *= (1.f/1024.f);
        *(float4*)&dst[w*64 + tid*4] = s;
    }
}

// ---------------------------------------------------------------------------
// Kernel 3: a_r = relu(q_r @ k_r^T)   (64x64x64 — trivial, fp32)
// ---------------------------------------------------------------------------
__global__ void ar_kernel()
{
    __shared__ float qs[NWIN*C], ks[NWIN*C];
    const int tid = threadIdx.x;
    for (int i = tid; i < NWIN*C; i += 256) { qs[i] = g_qr[i]; ks[i] = g_kr[i]; }
    __syncthreads();
    for (int e = tid; e < NWIN*NWIN; e += 256) {
        int i = e >> 6, j = e & 63;
        float s = 0.f;
        #pragma unroll
        for (int c = 0; c < 64; c++) s += qs[i*64 + c] * ks[j*64 + c];
        g_ar[e] = fmaxf(s, 0.f);
    }
}

// ---------------------------------------------------------------------------
// Kernel 4: q_m/k_m = a_r @ src. Split-A (a_r hi/lo) x single-tf32 B.
// grid (512, 2): 512 pos-tiles of 128. 8 warps (4m x 2n), warp tile 16x64.
// smem: Ah/Al[64][68], B[64][136]; stage [64][132]. ~70 KB -> 3 CTAs/SM.
// ---------------------------------------------------------------------------
#define MIX_AS 68
#define MIX_BS 136
#define MIX_SG 132
#define MIX_SMEM ((2*64*MIX_AS + 64*MIX_BS)*4)   // 69632 B

__global__ __launch_bounds__(256) void mix_kernel()
{
    extern __shared__ float sm[];
    uint32_t* Ah = (uint32_t*)sm;            // [64][68]
    uint32_t* Al = Ah + 64*MIX_AS;           // [64][68]
    uint32_t* Bs = Al + 64*MIX_AS;           // [64][136]
    float*    Sg = sm;                       // stage [64][132] (union)

    const int tid = threadIdx.x;
    const int warp = tid >> 5, lane = tid & 31;
    const int gid  = lane >> 2, tig = lane & 3;
    const int mwarp = warp >> 1;             // 0..3 -> 16 rows
    const int nwarp = warp & 1;              // 0..1 -> 64 cols
    const float* src = blockIdx.y ? g_k  : g_q;
    float*       dst = blockIdx.y ? g_km : g_qm;
    const int pos0 = blockIdx.x * 128;

    #pragma unroll
    for (int p = 0; p < 16; p++) {
        int e = tid + p*256;
        int i = e >> 6, j = e & 63;
        uint32_t hi, lo; split_tf32(g_ar[e], hi, lo);
        Ah[i*MIX_AS + j] = hi;
        Al[i*MIX_AS + j] = lo;
    }
    #pragma unroll
    for (int p = 0; p < 8; p++) {
        int idx = tid + p*256;               // 2048 float4
        int j = idx >> 5, f4 = idx & 31;
        float4 v = *(const float4*)&src[j*WELEMS + pos0 + f4*4];
        uint32_t* d = &Bs[j*MIX_BS + f4*4];
        d[0] = f2tf32(v.x); d[1] = f2tf32(v.y);
        d[2] = f2tf32(v.z); d[3] = f2tf32(v.w);
    }
    __syncthreads();

    float acc[8][4];
    #pragma unroll
    for (int nt = 0; nt < 8; nt++)
        #pragma unroll
        for (int e = 0; e < 4; e++) acc[nt][e] = 0.f;

    #pragma unroll
    for (int k0 = 0; k0 < 64; k0 += 8) {
        uint32_t ah[4], al[4];
        int r = mwarp*16 + gid;
        ah[0] = Ah[ r     *MIX_AS + k0 + tig];
        ah[1] = Ah[(r + 8)*MIX_AS + k0 + tig];
        ah[2] = Ah[ r     *MIX_AS + k0 + 4 + tig];
        ah[3] = Ah[(r + 8)*MIX_AS + k0 + 4 + tig];
        al[0] = Al[ r     *MIX_AS + k0 + tig];
        al[1] = Al[(r + 8)*MIX_AS + k0 + tig];
        al[2] = Al[ r     *MIX_AS + k0 + 4 + tig];
        al[3] = Al[(r + 8)*MIX_AS + k0 + 4 + tig];
        #pragma unroll
        for (int nt = 0; nt < 8; nt++) {
            int n = nwarp*64 + nt*8 + gid;
            uint32_t b[2];
            b[0] = Bs[(k0     + tig)*MIX_BS + n];
            b[1] = Bs[(k0 + 4 + tig)*MIX_BS + n];
            MMA_TF32(acc[nt], ah, b);
            MMA_TF32(acc[nt], al, b);
        }
    }
    __syncthreads();

    {
        int r = mwarp*16 + gid;
        #pragma unroll
        for (int nt = 0; nt < 8; nt++) {
            int n = nwarp*64 + nt*8 + 2*tig;
            Sg[ r     *MIX_SG + n    ] = acc[nt][0];
            Sg[ r     *MIX_SG + n + 1] = acc[nt][1];
            Sg[(r + 8)*MIX_SG + n    ] = acc[nt][2];
            Sg[(r + 8)*MIX_SG + n + 1] = acc[nt][3];
        }
    }
    __syncthreads();

    #pragma unroll
    for (int p = 0; p < 8; p++) {
        int idx = tid + p*256;
        int i = idx >> 5, f4 = idx & 31;
        float4 v = *(float4*)&Sg[i*MIX_SG + f4*4];
        *(float4*)&dst[i*WELEMS + pos0 + f4*4] = v;
    }
}

// ---------------------------------------------------------------------------
// Kernel 5 (dominant): O = relu(Qm @ Km^T) @ V via tf32 mma.sync.
// 128-row s-chunks, 1 CTA/SM (172 KB smem), 8 warps.
// Prefetch of next K/V chunk (FULL 128 rows: 8 passes) issued AFTER the
// relu->Ss store so it hides under MMA2 and never overlaps sacc liveness.
// ---------------------------------------------------------------------------
#define ATTN_SMEM ((3*128*68 + 128*132)*4)   // 172032 B

__global__ __launch_bounds__(256) void attn_kernel(float* __restrict__ out)
{
    extern __shared__ float sm[];
    uint32_t* Qsu = (uint32_t*)sm;           // [128][68]
    uint32_t* Ksu = Qsu + 128*68;            // [128][68]  ([s][c])
    uint32_t* Vsu = Ksu + 128*68;            // [128][68]  ([s][c])
    uint32_t* Ssu = Vsu + 128*68;            // [128][132]
    float*    Ss  = (float*)Ssu;

    const int bx  = blockIdx.x;
    const int w   = bx >> 3, seg = bx & 7;
    const int wy  = w >> 3,  wx  = w & 7;
    const int t0  = seg * 128;
    const int tid = threadIdx.x;
    const int warp = tid >> 5, lane = tid & 31;
    const int gid  = lane >> 2, tig = lane & 3;
    const int mwarp = warp >> 1;             // 0..3 -> 32 rows
    const int nwarp = warp & 1;              // 0..1

    const int psl = tid >> 4;                // prefetch row base (0..15)
    const int pc4 = (tid & 15) * 4;          // prefetch col

    // Q tile (128x64) -> tf32 smem, float4 loads
    #pragma unroll
    for (int p = 0; p < 8; p++) {
        int fidx = tid + p*256;
        int tl = fidx >> 4, c4 = (fidx & 15)*4;
        float4 v = *(const float4*)&g_qm[w*WELEMS + (t0 + tl)*64 + c4];
        uint32_t* d = &Qsu[tl*68 + c4];
        d[0] = f2tf32(v.x); d[1] = f2tf32(v.y); d[2] = f2tf32(v.z); d[3] = f2tf32(v.w);
    }

    // Prefetch chunk 0 K/V into registers (8 float4 each: all 128 rows)
    float4 kp[8], vp[8];
    #pragma unroll
    for (int p = 0; p < 8; p++) {
        int sl = psl + p*16;
        kp[p] = *(const float4*)&g_km[w*WELEMS + sl*64 + pc4];
        vp[p] = *(const float4*)&g_v [w*WELEMS + sl*64 + pc4];
    }

    float oacc[2][4][4];
    #pragma unroll
    for (int mt = 0; mt < 2; mt++)
        #pragma unroll
        for (int nt = 0; nt < 4; nt++)
            #pragma unroll
            for (int e = 0; e < 4; e++) oacc[mt][nt][e] = 0.f;

    #pragma unroll 1
    for (int chunk = 0; chunk < 8; chunk++) {
        __syncthreads();   // prev MMA2 done reading Ks/Vs/Ss; Qs fence on chunk 0

        // Commit prefetched regs -> smem (tf32), all 128 rows
        #pragma unroll
        for (int p = 0; p < 8; p++) {
            int sl = psl + p*16;
            uint32_t* dk = &Ksu[sl*68 + pc4];
            dk[0] = f2tf32(kp[p].x); dk[1] = f2tf32(kp[p].y);
            dk[2] = f2tf32(kp[p].z); dk[3] = f2tf32(kp[p].w);
            uint32_t* dv = &Vsu[sl*68 + pc4];
            dv[0] = f2tf32(vp[p].x); dv[1] = f2tf32(vp[p].y);
            dv[2] = f2tf32(vp[p].z); dv[3] = f2tf32(vp[p].w);
        }
        __syncthreads();

        // ---- MMA1: S(128x128) = Q @ K^T, warp tile 32x64 ----
        float sacc[2][8][4];
        #pragma unroll
        for (int mt = 0; mt < 2; mt++)
            #pragma unroll
            for (int nt = 0; nt < 8; nt++)
                #pragma unroll
                for (int e = 0; e < 4; e++) sacc[mt][nt][e] = 0.f;

        #pragma unroll
        for (int k0 = 0; k0 < 64; k0 += 8) {
            uint32_t a[2][4];
            #pragma unroll
            for (int mt = 0; mt < 2; mt++) {
                int r = mwarp*32 + mt*16 + gid;
                a[mt][0] = Qsu[ r     *68 + k0 + tig];
                a[mt][1] = Qsu[(r + 8)*68 + k0 + tig];
                a[mt][2] = Qsu[ r     *68 + k0 + 4 + tig];
                a[mt][3] = Qsu[(r + 8)*68 + k0 + 4 + tig];
            }
            #pragma unroll
            for (int nt = 0; nt < 8; nt++) {
                int s = nwarp*64 + nt*8 + gid;
                uint32_t b[2];
                b[0] = Ksu[s*68 + k0 + tig];
                b[1] = Ksu[s*68 + k0 + 4 + tig];
                MMA_TF32(sacc[0][nt], a[0], b);
                MMA_TF32(sacc[1][nt], a[1], b);
            }
        }

        // relu + tf32 -> Ss[t][s]   (sacc dies here)
        #pragma unroll
        for (int mt = 0; mt < 2; mt++) {
            int r = mwarp*32 + mt*16 + gid;
            #pragma unroll
            for (int nt = 0; nt < 8; nt++) {
                int cc = nwarp*64 + nt*8 + 2*tig;
                Ssu[ r     *132 + cc    ] = f2tf32(fmaxf(sacc[mt][nt][0], 0.f));
                Ssu[ r     *132 + cc + 1] = f2tf32(fmaxf(sacc[mt][nt][1], 0.f));
                Ssu[(r + 8)*132 + cc    ] = f2tf32(fmaxf(sacc[mt][nt][2], 0.f));
                Ssu[(r + 8)*132 + cc + 1] = f2tf32(fmaxf(sacc[mt][nt][3], 0.f));
            }
        }

        // Issue prefetch of NEXT chunk now (hides under MMA2; sacc is dead)
        if (chunk < 7) {
            const int sn = (chunk + 1) * 128;
            #pragma unroll
            for (int p = 0; p < 8; p++) {
                int sl = sn + psl + p*16;
                kp[p] = *(const float4*)&g_km[w*WELEMS + sl*64 + pc4];
                vp[p] = *(const float4*)&g_v [w*WELEMS + sl*64 + pc4];
            }
        }
        __syncthreads();

        // ---- MMA2: O(128x64) += S(128x128) @ V(128x64), warp tile 32x32 ----
        #pragma unroll
        for (int k0 = 0; k0 < 128; k0 += 8) {
            uint32_t a[2][4];
            #pragma unroll
            for (int mt = 0; mt < 2; mt++) {
                int r = mwarp*32 + mt*16 + gid;
                a[mt][0] = Ssu[ r     *132 + k0 + tig];
                a[mt][1] = Ssu[(r + 8)*132 + k0 + tig];
                a[mt][2] = Ssu[ r     *132 + k0 + 4 + tig];
                a[mt][3] = Ssu[(r + 8)*132 + k0 + 4 + tig];
            }
            #pragma unroll
            for (int nt = 0; nt < 4; nt++) {
                int c = nwarp*32 + nt*8 + gid;
                uint32_t b[2];
                b[0] = Vsu[(k0     + tig)*68 + c];
                b[1] = Vsu[(k0 + 4 + tig)*68 + c];
                MMA_TF32(oacc[0][nt], a[0], b);
                MMA_TF32(oacc[1][nt], a[1], b);
            }
        }
    }

    __syncthreads();
    // stage O [t][c] fp32, then coalesced NCHW-window stores
    #pragma unroll
    for (int mt = 0; mt < 2; mt++) {
        int r = mwarp*32 + mt*16 + gid;
        #pragma unroll
        for (int nt = 0; nt < 4; nt++) {
            int c = nwarp*32 + nt*8 + 2*tig;
            Ss[ r     *132 + c    ] = oacc[mt][nt][0];
            Ss[ r     *132 + c + 1] = oacc[mt][nt][1];
            Ss[(r + 8)*132 + c    ] = oacc[mt][nt][2];
            Ss[(r + 8)*132 + c + 1] = oacc[mt][nt][3];
        }
    }
    __syncthreads();

    #pragma unroll
    for (int i = 0; i < 32; i++) {
        int idx = tid + i*256;
        int ch = idx >> 7, tl = idx & 127;
        int t  = t0 + tl;
        out[ch*65536 + (wy*32 + (t>>5))*256 + wx*32 + (t&31)] = Ss[tl*132 + ch];
    }
}

// ---------------------------------------------------------------------------
extern "C" void kernel_launch(void* const* d_in, const int* in_sizes, int n_in,
                              void* d_out, int out_size)
{
    const float* x    = (const float*)d_in[0];
    const float* W    = (const float*)d_in[1];
    const float* bias = (const float*)d_in[2];
    float* out = (float*)d_out;

    cudaFuncSetAttribute(qkv_kernel,  cudaFuncAttributeMaxDynamicSharedMemorySize, QKV_SMEM);
    cudaFuncSetAttribute(mix_kernel,  cudaFuncAttributeMaxDynamicSharedMemorySize, MIX_SMEM);
    cudaFuncSetAttribute(attn_kernel, cudaFuncAttributeMaxDynamicSharedMemorySize, ATTN_SMEM);

    qkv_kernel <<<dim3(512, 2), 256, QKV_SMEM>>>(x, W, bias);
    mean_kernel<<<dim3(64, 2),  256>>>();
    ar_kernel  <<<1,            256>>>();
    mix_kernel <<<dim3(512, 2), 256, MIX_SMEM>>>();
    attn_kernel<<<512,          256, ATTN_SMEM>>>(out);
}

// round 10
// speedup vs baseline: 1.4761x; 1.3876x over previous
#include <cuda_runtime.h>
#include <cuda_fp16.h>
#include <cstdint>

// Problem constants: x (1,64,256,256), W (192,64), bias (192), 8x8 windows of 32x32.
#define NWIN 64
#define TOK  1024
#define C    64
#define WELEMS (TOK*C)          // 65536 floats per window per tensor

// Scratch (device globals — no allocation allowed)
__device__ float g_q [NWIN*WELEMS];
__device__ float g_k [NWIN*WELEMS];
__device__ float g_v [NWIN*WELEMS];
__device__ float g_qm[NWIN*WELEMS];
__device__ float g_km[NWIN*WELEMS];
__device__ float g_qr[NWIN*C];
__device__ float g_kr[NWIN*C];
__device__ float g_ar[NWIN*NWIN];

// ---------------------------------------------------------------------------
// tf32 helpers (legacy mma.sync path, used by qkv/mix)
// ---------------------------------------------------------------------------
__device__ __forceinline__ uint32_t f2tf32(float f) {
    uint32_t r;
    asm("cvt.rna.tf32.f32 %0, %1;" : "=r"(r) : "f"(f));
    return r;
}
__device__ __forceinline__ void split_tf32(float f, uint32_t& hi, uint32_t& lo) {
    hi = f2tf32(f);
    lo = f2tf32(f - __uint_as_float(hi));
}

#define MMA_TF32(d, a, b)                                                     \
    asm volatile(                                                             \
        "mma.sync.aligned.m16n8k8.row.col.f32.tf32.tf32.f32 "                 \
        "{%0,%1,%2,%3}, {%4,%5,%6,%7}, {%8,%9}, {%0,%1,%2,%3};"               \
        : "+f"((d)[0]), "+f"((d)[1]), "+f"((d)[2]), "+f"((d)[3])              \
        : "r"((a)[0]), "r"((a)[1]), "r"((a)[2]), "r"((a)[3]),                 \
          "r"((b)[0]), "r"((b)[1]))

// ---------------------------------------------------------------------------
// fp16 helpers (attn)
// ---------------------------------------------------------------------------
__device__ __forceinline__ uint32_t pack_half2(float lo, float hi) {
    uint32_t r;
    asm("cvt.rn.f16x2.f32 %0, %1, %2;" : "=r"(r) : "f"(hi), "f"(lo));
    return r;   // d.lo = lo, d.hi = hi
}

#define MMA_F16(d, a, b)                                                      \
    asm volatile(                                                             \
        "mma.sync.aligned.m16n8k16.row.col.f32.f16.f16.f32 "                  \
        "{%0,%1,%2,%3}, {%4,%5,%6,%7}, {%8,%9}, {%0,%1,%2,%3};"               \
        : "+f"((d)[0]), "+f"((d)[1]), "+f"((d)[2]), "+f"((d)[3])              \
        : "r"((a)[0]), "r"((a)[1]), "r"((a)[2]), "r"((a)[3]),                 \
          "r"((b)[0]), "r"((b)[1]))

__device__ __forceinline__ uint32_t smem_u32(const void* p) {
    uint32_t a;
    asm("{ .reg .u64 t; cvta.to.shared.u64 t, %1; cvt.u32.u64 %0, t; }"
        : "=r"(a) : "l"(p));
    return a;
}
__device__ __forceinline__ void ldsm_x2_trans(uint32_t& b0, uint32_t& b1, uint32_t addr) {
    asm volatile("ldmatrix.sync.aligned.m8n8.x2.trans.shared.b16 {%0,%1}, [%2];"
        : "=r"(b0), "=r"(b1) : "r"(addr));
}

// ---------------------------------------------------------------------------
// Kernel 1: qkv = gather(x) @ W^T + bias, split-tf32 (unchanged from R8)
// ---------------------------------------------------------------------------
#define QKV_XS 68
#define QKV_WS 104
#define QKV_SG 100
#define QKV_SMEM ((2*128*QKV_XS + 2*64*QKV_WS + 96)*4)

__global__ __launch_bounds__(256) void qkv_kernel(const float* __restrict__ x,
                                                  const float* __restrict__ W,
                                                  const float* __restrict__ bias)
{
    extern __shared__ float sm[];
    uint32_t* Xh = (uint32_t*)sm;
    uint32_t* Xl = Xh + 128*QKV_XS;
    uint32_t* Wh = Xl + 128*QKV_XS;
    uint32_t* Wl = Wh + 64*QKV_WS;
    float*    bs = (float*)(Wl + 64*QKV_WS);
    float*    Sg = sm;

    const int tt  = blockIdx.x;
    const int jh  = blockIdx.y;
    const int w   = tt >> 3, seg = tt & 7;
    const int wy  = w >> 3,  wx  = w & 7;
    const int t0  = seg * 128;
    const int tid = threadIdx.x;
    const int warp = tid >> 5, lane = tid & 31;
    const int gid  = lane >> 2, tig = lane & 3;
    const int mwarp = warp >> 1;
    const int nwarp = warp & 1;

    #pragma unroll
    for (int i = 0; i < 32; i++) {
        int idx = tid + i*256;
        int ch = idx >> 7, tl = idx & 127;
        int t  = t0 + tl;
        float v = x[ch*65536 + (wy*32 + (t>>5))*256 + wx*32 + (t&31)];
        uint32_t hi, lo; split_tf32(v, hi, lo);
        Xh[tl*QKV_XS + ch] = hi;
        Xl[tl*QKV_XS + ch] = lo;
    }
    #pragma unroll
    for (int i = 0; i < 24; i++) {
        int idx = tid + i*256;
        int ch = idx & 63, jl = idx >> 6;
        float v = W[(jh*96 + jl)*64 + ch];
        uint32_t hi, lo; split_tf32(v, hi, lo);
        Wh[ch*QKV_WS + jl] = hi;
        Wl[ch*QKV_WS + jl] = lo;
    }
    if (tid < 96) bs[tid] = bias[jh*96 + tid];
    __syncthreads();

    float acc[2][6][4];
    #pragma unroll
    for (int mt = 0; mt < 2; mt++)
        #pragma unroll
        for (int nt = 0; nt < 6; nt++)
            #pragma unroll
            for (int e = 0; e < 4; e++) acc[mt][nt][e] = 0.f;

    #pragma unroll
    for (int k0 = 0; k0 < 64; k0 += 8) {
        uint32_t ah[2][4], al[2][4];
        #pragma unroll
        for (int mt = 0; mt < 2; mt++) {
            int r = mwarp*32 + mt*16 + gid;
            ah[mt][0] = Xh[ r     *QKV_XS + k0 + tig];
            ah[mt][1] = Xh[(r + 8)*QKV_XS + k0 + tig];
            ah[mt][2] = Xh[ r     *QKV_XS + k0 + 4 + tig];
            ah[mt][3] = Xh[(r + 8)*QKV_XS + k0 + 4 + tig];
            al[mt][0] = Xl[ r     *QKV_XS + k0 + tig];
            al[mt][1] = Xl[(r + 8)*QKV_XS + k0 + tig];
            al[mt][2] = Xl[ r     *QKV_XS + k0 + 4 + tig];
            al[mt][3] = Xl[(r + 8)*QKV_XS + k0 + 4 + tig];
        }
        #pragma unroll
        for (int nt = 0; nt < 6; nt++) {
            int j = nwarp*48 + nt*8 + gid;
            uint32_t bh[2], bl[2];
            bh[0] = Wh[(k0     + tig)*QKV_WS + j];
            bh[1] = Wh[(k0 + 4 + tig)*QKV_WS + j];
            bl[0] = Wl[(k0     + tig)*QKV_WS + j];
            bl[1] = Wl[(k0 + 4 + tig)*QKV_WS + j];
            MMA_TF32(acc[0][nt], ah[0], bh);
            MMA_TF32(acc[0][nt], al[0], bh);
            MMA_TF32(acc[0][nt], ah[0], bl);
            MMA_TF32(acc[1][nt], ah[1], bh);
            MMA_TF32(acc[1][nt], al[1], bh);
            MMA_TF32(acc[1][nt], ah[1], bl);
        }
    }
    __syncthreads();

    #pragma unroll
    for (int mt = 0; mt < 2; mt++) {
        int r = mwarp*32 + mt*16 + gid;
        #pragma unroll
        for (int nt = 0; nt < 6; nt++) {
            int j = nwarp*48 + nt*8 + 2*tig;
            Sg[ r     *QKV_SG + j    ] = acc[mt][nt][0] + bs[j];
            Sg[ r     *QKV_SG + j + 1] = acc[mt][nt][1] + bs[j+1];
            Sg[(r + 8)*QKV_SG + j    ] = acc[mt][nt][2] + bs[j];
            Sg[(r + 8)*QKV_SG + j + 1] = acc[mt][nt][3] + bs[j+1];
        }
    }
    __syncthreads();

    #pragma unroll
    for (int p = 0; p < 12; p++) {
        int idx = tid + p*256;
        int t  = idx / 24, f4 = idx % 24;
        float4 v = *(float4*)&Sg[t*QKV_SG + f4*4];
        int jg = jh*96 + f4*4;
        float* dst = (jg < 64) ? g_q : (jg < 128) ? g_k : g_v;
        int jj = jg & 63;
        *(float4*)&dst[w*WELEMS + (t0 + t)*64 + jj] = v;
    }
}

// ---------------------------------------------------------------------------
// Kernel 2: means (unchanged)
// ---------------------------------------------------------------------------
__global__ void mean_kernel()
{
    __shared__ float4 red4[256];
    const int w   = blockIdx.x;
    const float* src = blockIdx.y ? g_k : g_q;
    float*       dst = blockIdx.y ? g_kr : g_qr;
    const int tid = threadIdx.x;
    const int l16 = tid & 15, g = tid >> 4;
    const float* base = src + w*WELEMS + l16*4;
    float4 acc = make_float4(0,0,0,0);
    #pragma unroll 4
    for (int t = g; t < 1024; t += 16) {
        float4 v = *(const float4*)&base[t*64];
        acc.x += v.x; acc.y += v.y; acc.z += v.z; acc.w += v.w;
    }
    red4[tid] = acc;
    __syncthreads();
    if (tid < 16) {
        float4 s = make_float4(0,0,0,0);
        #pragma unroll
        for (int gg = 0; gg < 16; gg++) {
            float4 v = red4[gg*16 + tid];
            s.x += v.x; s.y += v.y; s.z += v.z; s.w += v.w;
        }
        s.x *= (1.f/1024.f); s.y *= (1.f/1024.f);
        s.z *= (1.f/1024.f); s.w *= (1.f/1024.f);
        *(float4*)&dst[w*64 + tid*4] = s;
    }
}

// ---------------------------------------------------------------------------
// Kernel 3: a_r (unchanged)
// ---------------------------------------------------------------------------
__global__ void ar_kernel()
{
    __shared__ float qs[NWIN*C], ks[NWIN*C];
    const int tid = threadIdx.x;
    for (int i = tid; i < NWIN*C; i += 256) { qs[i] = g_qr[i]; ks[i] = g_kr[i]; }
    __syncthreads();
    for (int e = tid; e < NWIN*NWIN; e += 256) {
        int i = e >> 6, j = e & 63;
        float s = 0.f;
        #pragma unroll
        for (int c = 0; c < 64; c++) s += qs[i*64 + c] * ks[j*64 + c];
        g_ar[e] = fmaxf(s, 0.f);
    }
}

// ---------------------------------------------------------------------------
// Kernel 4: mix (unchanged from R8: split-A x single-tf32 B)
// ---------------------------------------------------------------------------
#define MIX_AS 68
#define MIX_BS 136
#define MIX_SG 132
#define MIX_SMEM ((2*64*MIX_AS + 64*MIX_BS)*4)

__global__ __launch_bounds__(256) void mix_kernel()
{
    extern __shared__ float sm[];
    uint32_t* Ah = (uint32_t*)sm;
    uint32_t* Al = Ah + 64*MIX_AS;
    uint32_t* Bs = Al + 64*MIX_AS;
    float*    Sg = sm;

    const int tid = threadIdx.x;
    const int warp = tid >> 5, lane = tid & 31;
    const int gid  = lane >> 2, tig = lane & 3;
    const int mwarp = warp >> 1;
    const int nwarp = warp & 1;
    const float* src = blockIdx.y ? g_k  : g_q;
    float*       dst = blockIdx.y ? g_km : g_qm;
    const int pos0 = blockIdx.x * 128;

    #pragma unroll
    for (int p = 0; p < 16; p++) {
        int e = tid + p*256;
        int i = e >> 6, j = e & 63;
        uint32_t hi, lo; split_tf32(g_ar[e], hi, lo);
        Ah[i*MIX_AS + j] = hi;
        Al[i*MIX_AS + j] = lo;
    }
    #pragma unroll
    for (int p = 0; p < 8; p++) {
        int idx = tid + p*256;
        int j = idx >> 5, f4 = idx & 31;
        float4 v = *(const float4*)&src[j*WELEMS + pos0 + f4*4];
        uint32_t* d = &Bs[j*MIX_BS + f4*4];
        d[0] = f2tf32(v.x); d[1] = f2tf32(v.y);
        d[2] = f2tf32(v.z); d[3] = f2tf32(v.w);
    }
    __syncthreads();

    float acc[8][4];
    #pragma unroll
    for (int nt = 0; nt < 8; nt++)
        #pragma unroll
        for (int e = 0; e < 4; e++) acc[nt][e] = 0.f;

    #pragma unroll
    for (int k0 = 0; k0 < 64; k0 += 8) {
        uint32_t ah[4], al[4];
        int r = mwarp*16 + gid;
        ah[0] = Ah[ r     *MIX_AS + k0 + tig];
        ah[1] = Ah[(r + 8)*MIX_AS + k0 + tig];
        ah[2] = Ah[ r     *MIX_AS + k0 + 4 + tig];
        ah[3] = Ah[(r + 8)*MIX_AS + k0 + 4 + tig];
        al[0] = Al[ r     *MIX_AS + k0 + tig];
        al[1] = Al[(r + 8)*MIX_AS + k0 + tig];
        al[2] = Al[ r     *MIX_AS + k0 + 4 + tig];
        al[3] = Al[(r + 8)*MIX_AS + k0 + 4 + tig];
        #pragma unroll
        for (int nt = 0; nt < 8; nt++) {
            int n = nwarp*64 + nt*8 + gid;
            uint32_t b[2];
            b[0] = Bs[(k0     + tig)*MIX_BS + n];
            b[1] = Bs[(k0 + 4 + tig)*MIX_BS + n];
            MMA_TF32(acc[nt], ah, b);
            MMA_TF32(acc[nt], al, b);
        }
    }
    __syncthreads();

    {
        int r = mwarp*16 + gid;
        #pragma unroll
        for (int nt = 0; nt < 8; nt++) {
            int n = nwarp*64 + nt*8 + 2*tig;
            Sg[ r     *MIX_SG + n    ] = acc[nt][0];
            Sg[ r     *MIX_SG + n + 1] = acc[nt][1];
            Sg[(r + 8)*MIX_SG + n    ] = acc[nt][2];
            Sg[(r + 8)*MIX_SG + n + 1] = acc[nt][3];
        }
    }
    __syncthreads();

    #pragma unroll
    for (int p = 0; p < 8; p++) {
        int idx = tid + p*256;
        int i = idx >> 5, f4 = idx & 31;
        float4 v = *(float4*)&Sg[i*MIX_SG + f4*4];
        *(float4*)&dst[i*WELEMS + pos0 + f4*4] = v;
    }
}

// ---------------------------------------------------------------------------
// Kernel 5 (dominant): O = relu(Qm Km^T) V via fp16 mma.sync m16n8k16.
// Scaling: q_m,k_m scaled x128 at fp16 convert -> S' = 16384*S (relu-safe,
// comfortably in fp16 normal range); O descaled by 1/16384 in fp32 epilogue.
// Q/K/V stored [s][c] fp16 pairs (conflict-free uint2 commits); MMA2 B frags
// from V via ldmatrix.x2.trans. smem 90KB -> 2 CTAs/SM hide load/epilogue.
// ---------------------------------------------------------------------------
#define AT_S  36    // Q/K/V word stride (32 words = 64 halfs + 4 pad)
#define AT_SS 68    // S word stride (64 words = 128 halfs + 4 pad)
#define ATTN_SMEM ((3*128*AT_S + 128*AT_SS)*4)   // 90112 B

__global__ __launch_bounds__(256, 2) void attn_kernel(float* __restrict__ out)
{
    extern __shared__ uint32_t smw[];
    uint32_t* Qw = smw;                  // [128][36] half2 words, scaled x128
    uint32_t* Kw = Qw + 128*AT_S;        // [128][36] scaled x128
    uint32_t* Vw = Kw + 128*AT_S;        // [128][36] unscaled, [s][c]
    uint32_t* Sw = Vw + 128*AT_S;        // [128][68] S' fp16 pairs
    float*    Sg = (float*)Sw;           // fp32 output stage (reuses Sw)

    const int bx = blockIdx.x;
    const int w  = bx >> 3, seg = bx & 7;
    const int wy = w >> 3,  wx  = w & 7;
    const int t0 = seg * 128;
    const int tid = threadIdx.x;
    const int warp = tid >> 5, lane = tid & 31;
    const int gid = lane >> 2, tig = lane & 3;
    const int mwarp = warp >> 1;         // 0..3 -> 32 rows
    const int nwarp = warp & 1;          // 0..1
    const int psl = tid >> 4;            // 0..15
    const int pcw = (tid & 15) * 2;      // word col (half col = pcw*2)

    const uint32_t vbase = smem_u32(Vw);

    // Q tile -> fp16 smem (scaled x128)
    #pragma unroll
    for (int p = 0; p < 8; p++) {
        int t = psl + p*16;
        float4 v = *(const float4*)&g_qm[w*WELEMS + (t0 + t)*64 + pcw*2];
        uint2 u;
        u.x = pack_half2(v.x*128.f, v.y*128.f);
        u.y = pack_half2(v.z*128.f, v.w*128.f);
        *(uint2*)&Qw[t*AT_S + pcw] = u;
    }

    float oacc[2][4][4];
    #pragma unroll
    for (int mt = 0; mt < 2; mt++)
        #pragma unroll
        for (int nt = 0; nt < 4; nt++)
            #pragma unroll
            for (int e = 0; e < 4; e++) oacc[mt][nt][e] = 0.f;

    #pragma unroll 1
    for (int chunk = 0; chunk < 8; chunk++) {
        const int s0 = chunk * 128;
        __syncthreads();   // prev MMA1/MMA2 done reading Kw/Vw/Sw; Qw fence @0

        // K (scaled) + V (unscaled) chunk -> fp16 smem, [s][c]
        #pragma unroll
        for (int p = 0; p < 8; p++) {
            int sl = psl + p*16;
            float4 kv = *(const float4*)&g_km[w*WELEMS + (s0 + sl)*64 + pcw*2];
            uint2 uk;
            uk.x = pack_half2(kv.x*128.f, kv.y*128.f);
            uk.y = pack_half2(kv.z*128.f, kv.w*128.f);
            *(uint2*)&Kw[sl*AT_S + pcw] = uk;
            float4 vv = *(const float4*)&g_v[w*WELEMS + (s0 + sl)*64 + pcw*2];
            uint2 uv;
            uv.x = pack_half2(vv.x, vv.y);
            uv.y = pack_half2(vv.z, vv.w);
            *(uint2*)&Vw[sl*AT_S + pcw] = uv;
        }
        __syncthreads();

        // ---- MMA1: S'(128x128) = Qs Ks^T, warp tile 32x64, 4 k-steps ----
        float sacc[2][8][4];
        #pragma unroll
        for (int mt = 0; mt < 2; mt++)
            #pragma unroll
            for (int nt = 0; nt < 8; nt++)
                #pragma unroll
                for (int e = 0; e < 4; e++) sacc[mt][nt][e] = 0.f;

        #pragma unroll
        for (int kk = 0; kk < 4; kk++) {
            int kw = kk*8;
            uint32_t a[2][4];
            #pragma unroll
            for (int mt = 0; mt < 2; mt++) {
                int r = mwarp*32 + mt*16 + gid;
                a[mt][0] = Qw[ r     *AT_S + kw + tig];
                a[mt][1] = Qw[(r + 8)*AT_S + kw + tig];
                a[mt][2] = Qw[ r     *AT_S + kw + 4 + tig];
                a[mt][3] = Qw[(r + 8)*AT_S + kw + 4 + tig];
            }
            #pragma unroll
            for (int nt = 0; nt < 8; nt++) {
                int s = nwarp*64 + nt*8 + gid;
                uint32_t b[2];
                b[0] = Kw[s*AT_S + kw + tig];
                b[1] = Kw[s*AT_S + kw + 4 + tig];
                MMA_F16(sacc[0][nt], a[0], b);
                MMA_F16(sacc[1][nt], a[1], b);
            }
        }

        // relu -> Sw fp16 pairs [t][s]
        #pragma unroll
        for (int mt = 0; mt < 2; mt++) {
            int r = mwarp*32 + mt*16 + gid;
            #pragma unroll
            for (int nt = 0; nt < 8; nt++) {
                int wc = nwarp*32 + nt*4 + tig;
                Sw[ r     *AT_SS + wc] = pack_half2(fmaxf(sacc[mt][nt][0], 0.f),
                                                    fmaxf(sacc[mt][nt][1], 0.f));
                Sw[(r + 8)*AT_SS + wc] = pack_half2(fmaxf(sacc[mt][nt][2], 0.f),
                                                    fmaxf(sacc[mt][nt][3], 0.f));
            }
        }
        __syncthreads();

        // ---- MMA2: O += S' V, warp tile 32x32, 8 k-steps ----
        #pragma unroll
        for (int kk = 0; kk < 8; kk++) {
            int kw = kk*8;
            uint32_t a[2][4];
            #pragma unroll
            for (int mt = 0; mt < 2; mt++) {
                int r = mwarp*32 + mt*16 + gid;
                a[mt][0] = Sw[ r     *AT_SS + kw + tig];
                a[mt][1] = Sw[(r + 8)*AT_SS + kw + tig];
                a[mt][2] = Sw[ r     *AT_SS + kw + 4 + tig];
                a[mt][3] = Sw[(r + 8)*AT_SS + kw + 4 + tig];
            }
            int krow = kk*16 + (lane & 7) + ((lane & 8) ? 8 : 0);
            #pragma unroll
            for (int nt = 0; nt < 4; nt++) {
                int c0 = nwarp*32 + nt*8;
                uint32_t b[2];
                uint32_t addr = vbase + (uint32_t)(krow*(AT_S*4) + c0*2);
                ldsm_x2_trans(b[0], b[1], addr);
                MMA_F16(oacc[0][nt], a[0], b);
                MMA_F16(oacc[1][nt], a[1], b);
            }
        }
    }

    __syncthreads();
    // stage O/16384 as fp32 [t][c], then coalesced NCHW-window stores
    #pragma unroll
    for (int mt = 0; mt < 2; mt++) {
        int r = mwarp*32 + mt*16 + gid;
        #pragma unroll
        for (int nt = 0; nt < 4; nt++) {
            int c = nwarp*32 + nt*8 + 2*tig;
            Sg[ r     *AT_SS + c    ] = oacc[mt][nt][0] * (1.f/16384.f);
            Sg[ r     *AT_SS + c + 1] = oacc[mt][nt][1] * (1.f/16384.f);
            Sg[(r + 8)*AT_SS + c    ] = oacc[mt][nt][2] * (1.f/16384.f);
            Sg[(r + 8)*AT_SS + c + 1] = oacc[mt][nt][3] * (1.f/16384.f);
        }
    }
    __syncthreads();

    #pragma unroll
    for (int i = 0; i < 32; i++) {
        int idx = tid + i*256;
        int ch = idx >> 7, tl = idx & 127;
        int t  = t0 + tl;
        out[ch*65536 + (wy*32 + (t>>5))*256 + wx*32 + (t&31)] = Sg[tl*AT_SS + ch];
    }
}

// ---------------------------------------------------------------------------
extern "C" void kernel_launch(void* const* d_in, const int* in_sizes, int n_in,
                              void* d_out, int out_size)
{
    const float* x    = (const float*)d_in[0];
    const float* W    = (const float*)d_in[1];
    const float* bias = (const float*)d_in[2];
    float* out = (float*)d_out;

    cudaFuncSetAttribute(qkv_kernel,  cudaFuncAttributeMaxDynamicSharedMemorySize, QKV_SMEM);
    cudaFuncSetAttribute(mix_kernel,  cudaFuncAttributeMaxDynamicSharedMemorySize, MIX_SMEM);
    cudaFuncSetAttribute(attn_kernel, cudaFuncAttributeMaxDynamicSharedMemorySize, ATTN_SMEM);

    qkv_kernel <<<dim3(512, 2), 256, QKV_SMEM>>>(x, W, bias);
    mean_kernel<<<dim3(64, 2),  256>>>();
    ar_kernel  <<<1,            256>>>();
    mix_kernel <<<dim3(512, 2), 256, MIX_SMEM>>>();
    attn_kernel<<<512,          256, ATTN_SMEM>>>(out);
}

// round 11
// speedup vs baseline: 1.6246x; 1.1006x over previous
#include <cuda_runtime.h>
#include <cuda_fp16.h>
#include <cstdint>

// Problem constants: x (1,64,256,256), W (192,64), bias (192), 8x8 windows of 32x32.
#define NWIN 64
#define TOK  1024
#define C    64
#define WELEMS (TOK*C)          // 65536 floats per window per tensor

// Scratch (device globals — no allocation allowed)
__device__ float    g_q   [NWIN*WELEMS];        // fp32 (mix B)
__device__ float    g_k   [NWIN*WELEMS];        // fp32 (mix B)
__device__ uint32_t g_vh  [NWIN*WELEMS/2];      // fp16 half2 [w][t][c/2]
__device__ uint32_t g_qmh [NWIN*WELEMS/2];      // fp16 half2, x128 scaled
__device__ uint32_t g_kmh [NWIN*WELEMS/2];      // fp16 half2, x128 scaled
__device__ float    g_part[1024*2*96];          // qkv per-block channel sums
__device__ float    g_ar  [NWIN*NWIN];

// ---------------------------------------------------------------------------
// tf32 helpers (legacy mma.sync path, used by qkv/mix)
// ---------------------------------------------------------------------------
__device__ __forceinline__ uint32_t f2tf32(float f) {
    uint32_t r;
    asm("cvt.rna.tf32.f32 %0, %1;" : "=r"(r) : "f"(f));
    return r;
}
__device__ __forceinline__ void split_tf32(float f, uint32_t& hi, uint32_t& lo) {
    hi = f2tf32(f);
    lo = f2tf32(f - __uint_as_float(hi));
}

#define MMA_TF32(d, a, b)                                                     \
    asm volatile(                                                             \
        "mma.sync.aligned.m16n8k8.row.col.f32.tf32.tf32.f32 "                 \
        "{%0,%1,%2,%3}, {%4,%5,%6,%7}, {%8,%9}, {%0,%1,%2,%3};"               \
        : "+f"((d)[0]), "+f"((d)[1]), "+f"((d)[2]), "+f"((d)[3])              \
        : "r"((a)[0]), "r"((a)[1]), "r"((a)[2]), "r"((a)[3]),                 \
          "r"((b)[0]), "r"((b)[1]))

// ---------------------------------------------------------------------------
// fp16 helpers (attn)
// ---------------------------------------------------------------------------
__device__ __forceinline__ uint32_t pack_half2(float lo, float hi) {
    uint32_t r;
    asm("cvt.rn.f16x2.f32 %0, %1, %2;" : "=r"(r) : "f"(hi), "f"(lo));
    return r;   // d.lo = lo, d.hi = hi
}

#define MMA_F16(d, a, b)                                                      \
    asm volatile(                                                             \
        "mma.sync.aligned.m16n8k16.row.col.f32.f16.f16.f32 "                  \
        "{%0,%1,%2,%3}, {%4,%5,%6,%7}, {%8,%9}, {%0,%1,%2,%3};"               \
        : "+f"((d)[0]), "+f"((d)[1]), "+f"((d)[2]), "+f"((d)[3])              \
        : "r"((a)[0]), "r"((a)[1]), "r"((a)[2]), "r"((a)[3]),                 \
          "r"((b)[0]), "r"((b)[1]))

__device__ __forceinline__ uint32_t smem_u32(const void* p) {
    uint32_t a;
    asm("{ .reg .u64 t; cvta.to.shared.u64 t, %1; cvt.u32.u64 %0, t; }"
        : "=r"(a) : "l"(p));
    return a;
}
__device__ __forceinline__ void ldsm_x2_trans(uint32_t& b0, uint32_t& b1, uint32_t addr) {
    asm volatile("ldmatrix.sync.aligned.m8n8.x2.trans.shared.b16 {%0,%1}, [%2];"
        : "=r"(b0), "=r"(b1) : "r"(addr));
}

// ---------------------------------------------------------------------------
// Kernel 1: qkv = gather(x) @ W^T + bias, split-tf32 (~fp32 accurate).
// grid (512, 2). New: v written as fp16; per-block channel partial sums
// (over the block's 128 tokens) written to g_part for the mean reduction.
// ---------------------------------------------------------------------------
#define QKV_XS 68
#define QKV_WS 104
#define QKV_SG 100
#define QKV_SMEM ((2*128*QKV_XS + 2*64*QKV_WS + 96)*4)

__global__ __launch_bounds__(256) void qkv_kernel(const float* __restrict__ x,
                                                  const float* __restrict__ W,
                                                  const float* __restrict__ bias)
{
    extern __shared__ float sm[];
    uint32_t* Xh = (uint32_t*)sm;
    uint32_t* Xl = Xh + 128*QKV_XS;
    uint32_t* Wh = Xl + 128*QKV_XS;
    uint32_t* Wl = Wh + 64*QKV_WS;
    float*    bs = (float*)(Wl + 64*QKV_WS);
    float*    Sg = sm;

    const int tt  = blockIdx.x;
    const int jh  = blockIdx.y;
    const int w   = tt >> 3, seg = tt & 7;
    const int wy  = w >> 3,  wx  = w & 7;
    const int t0  = seg * 128;
    const int tid = threadIdx.x;
    const int warp = tid >> 5, lane = tid & 31;
    const int gid  = lane >> 2, tig = lane & 3;
    const int mwarp = warp >> 1;
    const int nwarp = warp & 1;

    #pragma unroll
    for (int i = 0; i < 32; i++) {
        int idx = tid + i*256;
        int ch = idx >> 7, tl = idx & 127;
        int t  = t0 + tl;
        float v = x[ch*65536 + (wy*32 + (t>>5))*256 + wx*32 + (t&31)];
        uint32_t hi, lo; split_tf32(v, hi, lo);
        Xh[tl*QKV_XS + ch] = hi;
        Xl[tl*QKV_XS + ch] = lo;
    }
    #pragma unroll
    for (int i = 0; i < 24; i++) {
        int idx = tid + i*256;
        int ch = idx & 63, jl = idx >> 6;
        float v = W[(jh*96 + jl)*64 + ch];
        uint32_t hi, lo; split_tf32(v, hi, lo);
        Wh[ch*QKV_WS + jl] = hi;
        Wl[ch*QKV_WS + jl] = lo;
    }
    if (tid < 96) bs[tid] = bias[jh*96 + tid];
    __syncthreads();

    float acc[2][6][4];
    #pragma unroll
    for (int mt = 0; mt < 2; mt++)
        #pragma unroll
        for (int nt = 0; nt < 6; nt++)
            #pragma unroll
            for (int e = 0; e < 4; e++) acc[mt][nt][e] = 0.f;

    #pragma unroll
    for (int k0 = 0; k0 < 64; k0 += 8) {
        uint32_t ah[2][4], al[2][4];
        #pragma unroll
        for (int mt = 0; mt < 2; mt++) {
            int r = mwarp*32 + mt*16 + gid;
            ah[mt][0] = Xh[ r     *QKV_XS + k0 + tig];
            ah[mt][1] = Xh[(r + 8)*QKV_XS + k0 + tig];
            ah[mt][2] = Xh[ r     *QKV_XS + k0 + 4 + tig];
            ah[mt][3] = Xh[(r + 8)*QKV_XS + k0 + 4 + tig];
            al[mt][0] = Xl[ r     *QKV_XS + k0 + tig];
            al[mt][1] = Xl[(r + 8)*QKV_XS + k0 + tig];
            al[mt][2] = Xl[ r     *QKV_XS + k0 + 4 + tig];
            al[mt][3] = Xl[(r + 8)*QKV_XS + k0 + 4 + tig];
        }
        #pragma unroll
        for (int nt = 0; nt < 6; nt++) {
            int j = nwarp*48 + nt*8 + gid;
            uint32_t bh[2], bl[2];
            bh[0] = Wh[(k0     + tig)*QKV_WS + j];
            bh[1] = Wh[(k0 + 4 + tig)*QKV_WS + j];
            bl[0] = Wl[(k0     + tig)*QKV_WS + j];
            bl[1] = Wl[(k0 + 4 + tig)*QKV_WS + j];
            MMA_TF32(acc[0][nt], ah[0], bh);
            MMA_TF32(acc[0][nt], al[0], bh);
            MMA_TF32(acc[0][nt], ah[0], bl);
            MMA_TF32(acc[1][nt], ah[1], bh);
            MMA_TF32(acc[1][nt], al[1], bh);
            MMA_TF32(acc[1][nt], ah[1], bl);
        }
    }
    __syncthreads();

    #pragma unroll
    for (int mt = 0; mt < 2; mt++) {
        int r = mwarp*32 + mt*16 + gid;
        #pragma unroll
        for (int nt = 0; nt < 6; nt++) {
            int j = nwarp*48 + nt*8 + 2*tig;
            Sg[ r     *QKV_SG + j    ] = acc[mt][nt][0] + bs[j];
            Sg[ r     *QKV_SG + j + 1] = acc[mt][nt][1] + bs[j+1];
            Sg[(r + 8)*QKV_SG + j    ] = acc[mt][nt][2] + bs[j];
            Sg[(r + 8)*QKV_SG + j + 1] = acc[mt][nt][3] + bs[j+1];
        }
    }
    __syncthreads();

    // copy-out: q,k fp32; v fp16 half2
    #pragma unroll
    for (int p = 0; p < 12; p++) {
        int idx = tid + p*256;
        int t  = idx / 24, f4 = idx % 24;
        float4 v = *(float4*)&Sg[t*QKV_SG + f4*4];
        int jg = jh*96 + f4*4;
        if (jg < 128) {
            float* dst = (jg < 64) ? g_q : g_k;
            *(float4*)&dst[w*WELEMS + (t0 + t)*64 + (jg & 63)] = v;
        } else {
            int jj = jg - 128;
            uint2 u;
            u.x = pack_half2(v.x, v.y);
            u.y = pack_half2(v.z, v.w);
            *(uint2*)&g_vh[w*32768 + (t0 + t)*32 + (jj >> 1)] = u;
        }
    }

    // per-block channel sums over 128 tokens (deterministic mean reduction)
    if (tid < 96) {
        float s = 0.f;
        #pragma unroll 8
        for (int t = 0; t < 128; t++) s += Sg[t*QKV_SG + tid];
        g_part[(tt*2 + jh)*96 + tid] = s;
    }
}

// ---------------------------------------------------------------------------
// Kernel 2: a_r = relu(q_r @ k_r^T) from qkv partial sums. 1 block, 256 thr.
// q_r/k_r sums reduced over 8 segments; 1/1024^2 folded into the relu scale.
// ---------------------------------------------------------------------------
__global__ void ar_kernel()
{
    __shared__ float qs[NWIN*C], ks[NWIN*C];
    const int tid = threadIdx.x;
    for (int e = tid; e < NWIN*C; e += 256) {
        int w = e >> 6, c = e & 63;
        float sq = 0.f, sk = 0.f;
        #pragma unroll
        for (int seg = 0; seg < 8; seg++) {
            int tt = w*8 + seg;
            sq += g_part[(tt*2 + 0)*96 + c];
            sk += (c < 32) ? g_part[(tt*2 + 0)*96 + 64 + c]
                           : g_part[(tt*2 + 1)*96 + (c - 32)];
        }
        qs[e] = sq; ks[e] = sk;
    }
    __syncthreads();
    for (int e = tid; e < NWIN*NWIN; e += 256) {
        int i = e >> 6, j = e & 63;
        float s = 0.f;
        #pragma unroll
        for (int c = 0; c < 64; c++) s += qs[i*64 + c] * ks[j*64 + c];
        g_ar[e] = fmaxf(s, 0.f) * (1.f/1048576.f);
    }
}

// ---------------------------------------------------------------------------
// Kernel 3: q_m/k_m = a_r @ src (split-A tf32 x single-tf32 B).
// New: output packed fp16 half2, prescaled x128, staged for uint4 stores.
// ---------------------------------------------------------------------------
#define MIX_AS 68
#define MIX_BS 136
#define MIX_SW 68   // fp16 stage stride in words (64 + 4 pad)
#define MIX_SMEM ((2*64*MIX_AS + 64*MIX_BS)*4)

__global__ __launch_bounds__(256) void mix_kernel()
{
    extern __shared__ float sm[];
    uint32_t* Ah = (uint32_t*)sm;
    uint32_t* Al = Ah + 64*MIX_AS;
    uint32_t* Bs = Al + 64*MIX_AS;
    uint32_t* Sw = (uint32_t*)sm;            // fp16 stage [64][68] (union)

    const int tid = threadIdx.x;
    const int warp = tid >> 5, lane = tid & 31;
    const int gid  = lane >> 2, tig = lane & 3;
    const int mwarp = warp >> 1;             // 0..3 -> 16 rows
    const int nwarp = warp & 1;              // 0..1 -> 64 cols
    const float* src = blockIdx.y ? g_k  : g_q;
    uint32_t*    dst = blockIdx.y ? g_kmh : g_qmh;
    const int pos0 = blockIdx.x * 128;

    #pragma unroll
    for (int p = 0; p < 16; p++) {
        int e = tid + p*256;
        int i = e >> 6, j = e & 63;
        uint32_t hi, lo; split_tf32(g_ar[e], hi, lo);
        Ah[i*MIX_AS + j] = hi;
        Al[i*MIX_AS + j] = lo;
    }
    #pragma unroll
    for (int p = 0; p < 8; p++) {
        int idx = tid + p*256;
        int j = idx >> 5, f4 = idx & 31;
        float4 v = *(const float4*)&src[j*WELEMS + pos0 + f4*4];
        uint32_t* d = &Bs[j*MIX_BS + f4*4];
        d[0] = f2tf32(v.x); d[1] = f2tf32(v.y);
        d[2] = f2tf32(v.z); d[3] = f2tf32(v.w);
    }
    __syncthreads();

    float acc[8][4];
    #pragma unroll
    for (int nt = 0; nt < 8; nt++)
        #pragma unroll
        for (int e = 0; e < 4; e++) acc[nt][e] = 0.f;

    #pragma unroll
    for (int k0 = 0; k0 < 64; k0 += 8) {
        uint32_t ah[4], al[4];
        int r = mwarp*16 + gid;
        ah[0] = Ah[ r     *MIX_AS + k0 + tig];
        ah[1] = Ah[(r + 8)*MIX_AS + k0 + tig];
        ah[2] = Ah[ r     *MIX_AS + k0 + 4 + tig];
        ah[3] = Ah[(r + 8)*MIX_AS + k0 + 4 + tig];
        al[0] = Al[ r     *MIX_AS + k0 + tig];
        al[1] = Al[(r + 8)*MIX_AS + k0 + tig];
        al[2] = Al[ r     *MIX_AS + k0 + 4 + tig];
        al[3] = Al[(r + 8)*MIX_AS + k0 + 4 + tig];
        #pragma unroll
        for (int nt = 0; nt < 8; nt++) {
            int n = nwarp*64 + nt*8 + gid;
            uint32_t b[2];
            b[0] = Bs[(k0     + tig)*MIX_BS + n];
            b[1] = Bs[(k0 + 4 + tig)*MIX_BS + n];
            MMA_TF32(acc[nt], ah, b);
            MMA_TF32(acc[nt], al, b);
        }
    }
    __syncthreads();

    // stage fp16 (x128) pairs: elements (r,n),(r,n+1) -> one half2 word
    {
        int r = mwarp*16 + gid;
        #pragma unroll
        for (int nt = 0; nt < 8; nt++) {
            int wc = nwarp*32 + nt*4 + tig;     // (n)>>1, n = nwarp*64+nt*8+2tig
            Sw[ r     *MIX_SW + wc] = pack_half2(acc[nt][0]*128.f, acc[nt][1]*128.f);
            Sw[(r + 8)*MIX_SW + wc] = pack_half2(acc[nt][2]*128.f, acc[nt][3]*128.f);
        }
    }
    __syncthreads();

    // coalesced uint4 copy-out: 64 rows x 16 uint4
    #pragma unroll
    for (int p = 0; p < 4; p++) {
        int idx = tid + p*256;                  // < 1024
        int i = idx >> 4, w4 = idx & 15;
        uint4 v = *(uint4*)&Sw[i*MIX_SW + w4*4];
        ((uint4*)dst)[i*8192 + (pos0 >> 3) + w4] = v;
    }
}

// ---------------------------------------------------------------------------
// Kernel 4 (dominant): O = relu(Qm Km^T) V via fp16 mma.sync m16n8k16.
// Inputs already fp16: qm/km prescaled x128, v unscaled. Commit = raw copy.
// ---------------------------------------------------------------------------
#define AT_S  36    // Q/K/V word stride (32 words = 64 halfs + 4 pad)
#define AT_SS 68    // S word stride (64 words = 128 halfs + 4 pad)
#define ATTN_SMEM ((3*128*AT_S + 128*AT_SS)*4)   // 90112 B

__global__ __launch_bounds__(256, 2) void attn_kernel(float* __restrict__ out)
{
    extern __shared__ uint32_t smw[];
    uint32_t* Qw = smw;                  // [128][36] half2 words (scaled x128)
    uint32_t* Kw = Qw + 128*AT_S;        // [128][36] scaled x128
    uint32_t* Vw = Kw + 128*AT_S;        // [128][36] unscaled, [s][c]
    uint32_t* Sw = Vw + 128*AT_S;        // [128][68] S' fp16 pairs
    float*    Sg = (float*)Sw;           // fp32 output stage (reuses Sw)

    const int bx = blockIdx.x;
    const int w  = bx >> 3, seg = bx & 7;
    const int wy = w >> 3,  wx  = w & 7;
    const int t0 = seg * 128;
    const int tid = threadIdx.x;
    const int warp = tid >> 5, lane = tid & 31;
    const int gid = lane >> 2, tig = lane & 3;
    const int mwarp = warp >> 1;         // 0..3 -> 32 rows
    const int nwarp = warp & 1;          // 0..1
    const int psl = tid >> 4;            // 0..15
    const int pcw = (tid & 15) * 2;      // word col
    const int pu2 = tid & 15;            // uint2 col

    const uint32_t vbase = smem_u32(Vw);
    const uint2* qm2 = (const uint2*)g_qmh;
    const uint2* km2 = (const uint2*)g_kmh;
    const uint2* vv2 = (const uint2*)g_vh;

    // Q tile -> smem (raw fp16 copy)
    #pragma unroll
    for (int p = 0; p < 8; p++) {
        int t = psl + p*16;
        uint2 u = qm2[w*16384 + (t0 + t)*16 + pu2];
        Qw[t*AT_S + pcw]     = u.x;
        Qw[t*AT_S + pcw + 1] = u.y;
    }

    float oacc[2][4][4];
    #pragma unroll
    for (int mt = 0; mt < 2; mt++)
        #pragma unroll
        for (int nt = 0; nt < 4; nt++)
            #pragma unroll
            for (int e = 0; e < 4; e++) oacc[mt][nt][e] = 0.f;

    #pragma unroll 1
    for (int chunk = 0; chunk < 8; chunk++) {
        const int s0 = chunk * 128;
        __syncthreads();   // prev MMA1/MMA2 done reading Kw/Vw/Sw; Qw fence @0

        #pragma unroll
        for (int p = 0; p < 8; p++) {
            int sl = psl + p*16;
            uint2 uk = km2[w*16384 + (s0 + sl)*16 + pu2];
            Kw[sl*AT_S + pcw]     = uk.x;
            Kw[sl*AT_S + pcw + 1] = uk.y;
            uint2 uv = vv2[w*16384 + (s0 + sl)*16 + pu2];
            Vw[sl*AT_S + pcw]     = uv.x;
            Vw[sl*AT_S + pcw + 1] = uv.y;
        }
        __syncthreads();

        // ---- MMA1: S'(128x128) = Qs Ks^T, warp tile 32x64, 4 k-steps ----
        float sacc[2][8][4];
        #pragma unroll
        for (int mt = 0; mt < 2; mt++)
            #pragma unroll
            for (int nt = 0; nt < 8; nt++)
                #pragma unroll
                for (int e = 0; e < 4; e++) sacc[mt][nt][e] = 0.f;

        #pragma unroll
        for (int kk = 0; kk < 4; kk++) {
            int kw = kk*8;
            uint32_t a[2][4];
            #pragma unroll
            for (int mt = 0; mt < 2; mt++) {
                int r = mwarp*32 + mt*16 + gid;
                a[mt][0] = Qw[ r     *AT_S + kw + tig];
                a[mt][1] = Qw[(r + 8)*AT_S + kw + tig];
                a[mt][2] = Qw[ r     *AT_S + kw + 4 + tig];
                a[mt][3] = Qw[(r + 8)*AT_S + kw + 4 + tig];
            }
            #pragma unroll
            for (int nt = 0; nt < 8; nt++) {
                int s = nwarp*64 + nt*8 + gid;
                uint32_t b[2];
                b[0] = Kw[s*AT_S + kw + tig];
                b[1] = Kw[s*AT_S + kw + 4 + tig];
                MMA_F16(sacc[0][nt], a[0], b);
                MMA_F16(sacc[1][nt], a[1], b);
            }
        }

        // relu -> Sw fp16 pairs [t][s]
        #pragma unroll
        for (int mt = 0; mt < 2; mt++) {
            int r = mwarp*32 + mt*16 + gid;
            #pragma unroll
            for (int nt = 0; nt < 8; nt++) {
                int wc = nwarp*32 + nt*4 + tig;
                Sw[ r     *AT_SS + wc] = pack_half2(fmaxf(sacc[mt][nt][0], 0.f),
                                                    fmaxf(sacc[mt][nt][1], 0.f));
                Sw[(r + 8)*AT_SS + wc] = pack_half2(fmaxf(sacc[mt][nt][2], 0.f),
                                                    fmaxf(sacc[mt][nt][3], 0.f));
            }
        }
        __syncthreads();

        // ---- MMA2: O += S' V, warp tile 32x32, 8 k-steps ----
        #pragma unroll
        for (int kk = 0; kk < 8; kk++) {
            int kw = kk*8;
            uint32_t a[2][4];
            #pragma unroll
            for (int mt = 0; mt < 2; mt++) {
                int r = mwarp*32 + mt*16 + gid;
                a[mt][0] = Sw[ r     *AT_SS + kw + tig];
                a[mt][1] = Sw[(r + 8)*AT_SS + kw + tig];
                a[mt][2] = Sw[ r     *AT_SS + kw + 4 + tig];
                a[mt][3] = Sw[(r + 8)*AT_SS + kw + 4 + tig];
            }
            int krow = kk*16 + (lane & 7) + ((lane & 8) ? 8 : 0);
            #pragma unroll
            for (int nt = 0; nt < 4; nt++) {
                int c0 = nwarp*32 + nt*8;
                uint32_t b[2];
                uint32_t addr = vbase + (uint32_t)(krow*(AT_S*4) + c0*2);
                ldsm_x2_trans(b[0], b[1], addr);
                MMA_F16(oacc[0][nt], a[0], b);
                MMA_F16(oacc[1][nt], a[1], b);
            }
        }
    }

    __syncthreads();
    // stage O/16384 as fp32 [t][c], then coalesced NCHW-window stores
    #pragma unroll
    for (int mt = 0; mt < 2; mt++) {
        int r = mwarp*32 + mt*16 + gid;
        #pragma unroll
        for (int nt = 0; nt < 4; nt++) {
            int c = nwarp*32 + nt*8 + 2*tig;
            Sg[ r     *AT_SS + c    ] = oacc[mt][nt][0] * (1.f/16384.f);
            Sg[ r     *AT_SS + c + 1] = oacc[mt][nt][1] * (1.f/16384.f);
            Sg[(r + 8)*AT_SS + c    ] = oacc[mt][nt][2] * (1.f/16384.f);
            Sg[(r + 8)*AT_SS + c + 1] = oacc[mt][nt][3] * (1.f/16384.f);
        }
    }
    __syncthreads();

    #pragma unroll
    for (int i = 0; i < 32; i++) {
        int idx = tid + i*256;
        int ch = idx >> 7, tl = idx & 127;
        int t  = t0 + tl;
        out[ch*65536 + (wy*32 + (t>>5))*256 + wx*32 + (t&31)] = Sg[tl*AT_SS + ch];
    }
}

// ---------------------------------------------------------------------------
extern "C" void kernel_launch(void* const* d_in, const int* in_sizes, int n_in,
                              void* d_out, int out_size)
{
    const float* x    = (const float*)d_in[0];
    const float* W    = (const float*)d_in[1];
    const float* bias = (const float*)d_in[2];
    float* out = (float*)d_out;

    cudaFuncSetAttribute(qkv_kernel,  cudaFuncAttributeMaxDynamicSharedMemorySize, QKV_SMEM);
    cudaFuncSetAttribute(mix_kernel,  cudaFuncAttributeMaxDynamicSharedMemorySize, MIX_SMEM);
    cudaFuncSetAttribute(attn_kernel, cudaFuncAttributeMaxDynamicSharedMemorySize, ATTN_SMEM);

    qkv_kernel <<<dim3(512, 2), 256, QKV_SMEM>>>(x, W, bias);
    ar_kernel  <<<1,            256>>>();
    mix_kernel <<<dim3(512, 2), 256, MIX_SMEM>>>();
    attn_kernel<<<512,          256, ATTN_SMEM>>>(out);
}

// round 12
// speedup vs baseline: 1.7821x; 1.0970x over previous
#include <cuda_runtime.h>
#include <cuda_fp16.h>
#include <cstdint>

// Problem constants: x (1,64,256,256), W (192,64), bias (192), 8x8 windows of 32x32.
#define NWIN 64
#define TOK  1024
#define C    64
#define WELEMS (TOK*C)          // 65536 floats per window per tensor

// Scratch (device globals — no allocation allowed)
__device__ uint32_t g_qh  [NWIN*WELEMS/2];      // fp16 half2 [w][t][c/2]
__device__ uint32_t g_kh  [NWIN*WELEMS/2];      // fp16 half2
__device__ uint32_t g_vh  [NWIN*WELEMS/2];      // fp16 half2
__device__ uint32_t g_qmh [NWIN*WELEMS/2];      // fp16 half2, x128 scaled
__device__ uint32_t g_kmh [NWIN*WELEMS/2];      // fp16 half2, x128 scaled
__device__ float    g_part[1024*2*96];          // qkv per-block channel sums
__device__ float    g_ar  [NWIN*NWIN];          // x64 prescaled

// ---------------------------------------------------------------------------
// tf32 helpers (qkv only)
// ---------------------------------------------------------------------------
__device__ __forceinline__ uint32_t f2tf32(float f) {
    uint32_t r;
    asm("cvt.rna.tf32.f32 %0, %1;" : "=r"(r) : "f"(f));
    return r;
}
__device__ __forceinline__ void split_tf32(float f, uint32_t& hi, uint32_t& lo) {
    hi = f2tf32(f);
    lo = f2tf32(f - __uint_as_float(hi));
}

#define MMA_TF32(d, a, b)                                                     \
    asm volatile(                                                             \
        "mma.sync.aligned.m16n8k8.row.col.f32.tf32.tf32.f32 "                 \
        "{%0,%1,%2,%3}, {%4,%5,%6,%7}, {%8,%9}, {%0,%1,%2,%3};"               \
        : "+f"((d)[0]), "+f"((d)[1]), "+f"((d)[2]), "+f"((d)[3])              \
        : "r"((a)[0]), "r"((a)[1]), "r"((a)[2]), "r"((a)[3]),                 \
          "r"((b)[0]), "r"((b)[1]))

// ---------------------------------------------------------------------------
// fp16 helpers
// ---------------------------------------------------------------------------
__device__ __forceinline__ uint32_t pack_half2(float lo, float hi) {
    uint32_t r;
    asm("cvt.rn.f16x2.f32 %0, %1, %2;" : "=r"(r) : "f"(hi), "f"(lo));
    return r;   // d.lo = lo, d.hi = hi
}

#define MMA_F16(d, a, b)                                                      \
    asm volatile(                                                             \
        "mma.sync.aligned.m16n8k16.row.col.f32.f16.f16.f32 "                  \
        "{%0,%1,%2,%3}, {%4,%5,%6,%7}, {%8,%9}, {%0,%1,%2,%3};"               \
        : "+f"((d)[0]), "+f"((d)[1]), "+f"((d)[2]), "+f"((d)[3])              \
        : "r"((a)[0]), "r"((a)[1]), "r"((a)[2]), "r"((a)[3]),                 \
          "r"((b)[0]), "r"((b)[1]))

__device__ __forceinline__ uint32_t smem_u32(const void* p) {
    uint32_t a;
    asm("{ .reg .u64 t; cvta.to.shared.u64 t, %1; cvt.u32.u64 %0, t; }"
        : "=r"(a) : "l"(p));
    return a;
}
__device__ __forceinline__ void ldsm_x4(uint32_t* r, uint32_t addr) {
    asm volatile("ldmatrix.sync.aligned.m8n8.x4.shared.b16 {%0,%1,%2,%3}, [%4];"
        : "=r"(r[0]), "=r"(r[1]), "=r"(r[2]), "=r"(r[3]) : "r"(addr));
}
__device__ __forceinline__ void ldsm_x4_trans(uint32_t* r, uint32_t addr) {
    asm volatile("ldmatrix.sync.aligned.m8n8.x4.trans.shared.b16 {%0,%1,%2,%3}, [%4];"
        : "=r"(r[0]), "=r"(r[1]), "=r"(r[2]), "=r"(r[3]) : "r"(addr));
}

// ---------------------------------------------------------------------------
// Kernel 1: qkv = gather(x) @ W^T + bias, split-tf32 (~fp32 accurate).
// Outputs q/k/v all as packed fp16 half2. Per-block channel sums -> g_part.
// ---------------------------------------------------------------------------
#define QKV_XS 68
#define QKV_WS 104
#define QKV_SG 100
#define QKV_SMEM ((2*128*QKV_XS + 2*64*QKV_WS + 96)*4)

__global__ __launch_bounds__(256) void qkv_kernel(const float* __restrict__ x,
                                                  const float* __restrict__ W,
                                                  const float* __restrict__ bias)
{
    extern __shared__ float sm[];
    uint32_t* Xh = (uint32_t*)sm;
    uint32_t* Xl = Xh + 128*QKV_XS;
    uint32_t* Wh = Xl + 128*QKV_XS;
    uint32_t* Wl = Wh + 64*QKV_WS;
    float*    bs = (float*)(Wl + 64*QKV_WS);
    float*    Sg = sm;

    const int tt  = blockIdx.x;
    const int jh  = blockIdx.y;
    const int w   = tt >> 3, seg = tt & 7;
    const int wy  = w >> 3,  wx  = w & 7;
    const int t0  = seg * 128;
    const int tid = threadIdx.x;
    const int warp = tid >> 5, lane = tid & 31;
    const int gid  = lane >> 2, tig = lane & 3;
    const int mwarp = warp >> 1;
    const int nwarp = warp & 1;

    #pragma unroll
    for (int i = 0; i < 32; i++) {
        int idx = tid + i*256;
        int ch = idx >> 7, tl = idx & 127;
        int t  = t0 + tl;
        float v = x[ch*65536 + (wy*32 + (t>>5))*256 + wx*32 + (t&31)];
        uint32_t hi, lo; split_tf32(v, hi, lo);
        Xh[tl*QKV_XS + ch] = hi;
        Xl[tl*QKV_XS + ch] = lo;
    }
    #pragma unroll
    for (int i = 0; i < 24; i++) {
        int idx = tid + i*256;
        int ch = idx & 63, jl = idx >> 6;
        float v = W[(jh*96 + jl)*64 + ch];
        uint32_t hi, lo; split_tf32(v, hi, lo);
        Wh[ch*QKV_WS + jl] = hi;
        Wl[ch*QKV_WS + jl] = lo;
    }
    if (tid < 96) bs[tid] = bias[jh*96 + tid];
    __syncthreads();

    float acc[2][6][4];
    #pragma unroll
    for (int mt = 0; mt < 2; mt++)
        #pragma unroll
        for (int nt = 0; nt < 6; nt++)
            #pragma unroll
            for (int e = 0; e < 4; e++) acc[mt][nt][e] = 0.f;

    #pragma unroll
    for (int k0 = 0; k0 < 64; k0 += 8) {
        uint32_t ah[2][4], al[2][4];
        #pragma unroll
        for (int mt = 0; mt < 2; mt++) {
            int r = mwarp*32 + mt*16 + gid;
            ah[mt][0] = Xh[ r     *QKV_XS + k0 + tig];
            ah[mt][1] = Xh[(r + 8)*QKV_XS + k0 + tig];
            ah[mt][2] = Xh[ r     *QKV_XS + k0 + 4 + tig];
            ah[mt][3] = Xh[(r + 8)*QKV_XS + k0 + 4 + tig];
            al[mt][0] = Xl[ r     *QKV_XS + k0 + tig];
            al[mt][1] = Xl[(r + 8)*QKV_XS + k0 + tig];
            al[mt][2] = Xl[ r     *QKV_XS + k0 + 4 + tig];
            al[mt][3] = Xl[(r + 8)*QKV_XS + k0 + 4 + tig];
        }
        #pragma unroll
        for (int nt = 0; nt < 6; nt++) {
            int j = nwarp*48 + nt*8 + gid;
            uint32_t bh[2], bl[2];
            bh[0] = Wh[(k0     + tig)*QKV_WS + j];
            bh[1] = Wh[(k0 + 4 + tig)*QKV_WS + j];
            bl[0] = Wl[(k0     + tig)*QKV_WS + j];
            bl[1] = Wl[(k0 + 4 + tig)*QKV_WS + j];
            MMA_TF32(acc[0][nt], ah[0], bh);
            MMA_TF32(acc[0][nt], al[0], bh);
            MMA_TF32(acc[0][nt], ah[0], bl);
            MMA_TF32(acc[1][nt], ah[1], bh);
            MMA_TF32(acc[1][nt], al[1], bh);
            MMA_TF32(acc[1][nt], ah[1], bl);
        }
    }
    __syncthreads();

    #pragma unroll
    for (int mt = 0; mt < 2; mt++) {
        int r = mwarp*32 + mt*16 + gid;
        #pragma unroll
        for (int nt = 0; nt < 6; nt++) {
            int j = nwarp*48 + nt*8 + 2*tig;
            Sg[ r     *QKV_SG + j    ] = acc[mt][nt][0] + bs[j];
            Sg[ r     *QKV_SG + j + 1] = acc[mt][nt][1] + bs[j+1];
            Sg[(r + 8)*QKV_SG + j    ] = acc[mt][nt][2] + bs[j];
            Sg[(r + 8)*QKV_SG + j + 1] = acc[mt][nt][3] + bs[j+1];
        }
    }
    __syncthreads();

    // copy-out: q/k/v as packed fp16
    #pragma unroll
    for (int p = 0; p < 12; p++) {
        int idx = tid + p*256;
        int t  = idx / 24, f4 = idx % 24;
        float4 v = *(float4*)&Sg[t*QKV_SG + f4*4];
        int jg = jh*96 + f4*4;
        uint32_t* dst = (jg < 64) ? g_qh : (jg < 128) ? g_kh : g_vh;
        int jj = jg & 63;
        uint2 u;
        u.x = pack_half2(v.x, v.y);
        u.y = pack_half2(v.z, v.w);
        *(uint2*)&dst[w*32768 + (t0 + t)*32 + (jj >> 1)] = u;
    }

    // per-block channel sums over 128 tokens (deterministic mean reduction)
    if (tid < 96) {
        float s = 0.f;
        #pragma unroll 8
        for (int t = 0; t < 128; t++) s += Sg[t*QKV_SG + tid];
        g_part[(tt*2 + jh)*96 + tid] = s;
    }
}

// ---------------------------------------------------------------------------
// Kernel 2: a_r = relu(q_r @ k_r^T) from qkv partial sums. Output x64
// prescaled (mix packs x2 -> net x128 for attn).
// ---------------------------------------------------------------------------
__global__ void ar_kernel()
{
    __shared__ float qs[NWIN*C], ks[NWIN*C];
    const int tid = threadIdx.x;
    for (int e = tid; e < NWIN*C; e += 256) {
        int w = e >> 6, c = e & 63;
        float sq = 0.f, sk = 0.f;
        #pragma unroll
        for (int seg = 0; seg < 8; seg++) {
            int tt = w*8 + seg;
            sq += g_part[(tt*2 + 0)*96 + c];
            sk += (c < 32) ? g_part[(tt*2 + 0)*96 + 64 + c]
                           : g_part[(tt*2 + 1)*96 + (c - 32)];
        }
        qs[e] = sq; ks[e] = sk;
    }
    __syncthreads();
    for (int e = tid; e < NWIN*NWIN; e += 256) {
        int i = e >> 6, j = e & 63;
        float s = 0.f;
        #pragma unroll
        for (int c = 0; c < 64; c++) s += qs[i*64 + c] * ks[j*64 + c];
        g_ar[e] = fmaxf(s, 0.f) * (1.f/16384.f);   // (1/1024^2) * 64
    }
}

// ---------------------------------------------------------------------------
// Kernel 3: q_m/k_m = a_r @ src, fp16 MMA (A = split-fp16 a_r, B = fp16 q/k).
// grid (512, 2). Warp tile m16 x n64. Output packed fp16 x128 net scale.
// ---------------------------------------------------------------------------
#define MIX_AW 36   // A half2 words per row (32 + 4 pad)
#define MIX_BW 68   // B half2 words per row (64 + 4 pad)
#define MIX_SW 68
#define MIX_SMEM ((2*64*MIX_AW + 64*MIX_BW)*4)   // 35840 B

__global__ __launch_bounds__(256) void mix_kernel()
{
    extern __shared__ uint32_t smw[];
    uint32_t* Ah = smw;                   // [64][36] half2 (hi)
    uint32_t* Al = Ah + 64*MIX_AW;        // [64][36] half2 (lo)
    uint32_t* Bs = Al + 64*MIX_AW;        // [64][68] half2 [j][pos]
    uint32_t* Sw = smw;                   // fp16 stage [64][68] (union w/ Ah+Al)

    const int tid = threadIdx.x;
    const int warp = tid >> 5, lane = tid & 31;
    const int gid  = lane >> 2, tig = lane & 3;
    const int mwarp = warp >> 1;          // 0..3 -> 16 rows
    const int nwarp = warp & 1;           // 0..1 -> 64 pos
    const int l8 = lane & 7, lhi = (lane >> 3) & 1, lcol = lane >> 4;
    const uint2* srch = (const uint2*)(blockIdx.y ? g_kh : g_qh);
    uint32_t*    dst  = blockIdx.y ? g_kmh : g_qmh;
    const int pos0 = blockIdx.x * 128;

    // A: a_r split to fp16 hi/lo, packed along j
    #pragma unroll
    for (int p = 0; p < 8; p++) {
        int idx = tid + p*256;            // 2048 words
        int i = idx >> 5, jw = idx & 31;
        float v0 = g_ar[i*64 + jw*2], v1 = g_ar[i*64 + jw*2 + 1];
        float h0 = __half2float(__float2half_rn(v0));
        float h1 = __half2float(__float2half_rn(v1));
        Ah[i*MIX_AW + jw] = pack_half2(v0, v1);
        Al[i*MIX_AW + jw] = pack_half2(v0 - h0, v1 - h1);
    }
    // B: raw fp16 copy [j][pos]
    #pragma unroll
    for (int p = 0; p < 8; p++) {
        int idx = tid + p*256;            // 2048 uint2
        int j = idx >> 5, u2 = idx & 31;
        uint2 u = srch[j*16384 + (pos0 >> 2) + u2];
        *(uint2*)&Bs[j*MIX_BW + u2*2] = u;
    }
    __syncthreads();

    float acc[8][4];
    #pragma unroll
    for (int nt = 0; nt < 8; nt++)
        #pragma unroll
        for (int e = 0; e < 4; e++) acc[nt][e] = 0.f;

    const uint32_t bbase = smem_u32(Bs);
    const int r = mwarp*16 + gid;

    #pragma unroll
    for (int kk = 0; kk < 4; kk++) {
        uint32_t ah[4], al[4];
        ah[0] = Ah[ r     *MIX_AW + kk*8 + tig];
        ah[1] = Ah[(r + 8)*MIX_AW + kk*8 + tig];
        ah[2] = Ah[ r     *MIX_AW + kk*8 + 4 + tig];
        ah[3] = Ah[(r + 8)*MIX_AW + kk*8 + 4 + tig];
        al[0] = Al[ r     *MIX_AW + kk*8 + tig];
        al[1] = Al[(r + 8)*MIX_AW + kk*8 + tig];
        al[2] = Al[ r     *MIX_AW + kk*8 + 4 + tig];
        al[3] = Al[(r + 8)*MIX_AW + kk*8 + 4 + tig];
        #pragma unroll
        for (int ntv = 0; ntv < 4; ntv++) {
            int n0 = nwarp*64 + ntv*16;
            uint32_t b[4];
            ldsm_x4_trans(b, bbase + (uint32_t)((kk*16 + l8 + lhi*8)*(MIX_BW*4)
                                                + (n0 + lcol*8)*2));
            uint32_t b01[2] = {b[0], b[1]}, b23[2] = {b[2], b[3]};
            MMA_F16(acc[2*ntv],     ah, b01);
            MMA_F16(acc[2*ntv],     al, b01);
            MMA_F16(acc[2*ntv + 1], ah, b23);
            MMA_F16(acc[2*ntv + 1], al, b23);
        }
    }
    __syncthreads();

    // stage fp16 (x2 -> net x128) pairs
    #pragma unroll
    for (int nt = 0; nt < 8; nt++) {
        int wc = nwarp*32 + nt*4 + tig;
        Sw[ r     *MIX_SW + wc] = pack_half2(acc[nt][0]*2.f, acc[nt][1]*2.f);
        Sw[(r + 8)*MIX_SW + wc] = pack_half2(acc[nt][2]*2.f, acc[nt][3]*2.f);
    }
    __syncthreads();

    // coalesced uint4 copy-out: 64 rows x 16 uint4
    #pragma unroll
    for (int p = 0; p < 4; p++) {
        int idx = tid + p*256;
        int i = idx >> 4, w4 = idx & 15;
        uint4 v = *(uint4*)&Sw[i*MIX_SW + w4*4];
        ((uint4*)dst)[i*8192 + (pos0 >> 3) + w4] = v;
    }
}

// ---------------------------------------------------------------------------
// Kernel 4 (dominant): O = relu(Qm Km^T) V via fp16 mma, S register-resident.
// Each warp owns m16 rows x full n128 of S -> MMA1 c-frags ARE MMA2 a-frags
// after relu+pack (no S smem, one sync saved per chunk). ldmatrix.x4 frags.
// smem 55KB, 2 CTAs/SM.
// ---------------------------------------------------------------------------
#define AT_S  36    // Q/K/V word stride
#define AT_SG 68    // output stage stride (floats)
#define ATTN_SMEM (3*128*AT_S*4)   // 55296 B

__global__ __launch_bounds__(256, 2) void attn_kernel(float* __restrict__ out)
{
    extern __shared__ uint32_t smw[];
    uint32_t* Qw = smw;                  // [128][36] half2 (x128)
    uint32_t* Kw = Qw + 128*AT_S;        // [128][36] (x128)
    uint32_t* Vw = Kw + 128*AT_S;        // [128][36] unscaled
    float*    Sg = (float*)smw;          // output stage (reuses Qw/Kw)

    const int bx = blockIdx.x;
    const int w  = bx >> 3, seg = bx & 7;
    const int wy = w >> 3,  wx  = w & 7;
    const int t0 = seg * 128;
    const int tid = threadIdx.x;
    const int warp = tid >> 5, lane = tid & 31;
    const int gid = lane >> 2, tig = lane & 3;
    const int r0 = warp*16;              // warp's m rows
    const int l8 = lane & 7, lhi = (lane >> 3) & 1, lcol = lane >> 4;
    const int psl = tid >> 4;            // 0..15
    const int pcw = (tid & 15) * 2;      // word col
    const int pu2 = tid & 15;            // uint2 col

    const uint32_t qbase = smem_u32(Qw);
    const uint32_t kbase = smem_u32(Kw);
    const uint32_t vbase = smem_u32(Vw);
    const uint2* qm2 = (const uint2*)g_qmh;
    const uint2* km2 = (const uint2*)g_kmh;
    const uint2* vv2 = (const uint2*)g_vh;

    // Q tile -> smem (raw fp16 copy)
    #pragma unroll
    for (int p = 0; p < 8; p++) {
        int t = psl + p*16;
        uint2 u = qm2[w*16384 + (t0 + t)*16 + pu2];
        Qw[t*AT_S + pcw]     = u.x;
        Qw[t*AT_S + pcw + 1] = u.y;
    }

    float oacc[8][4];
    #pragma unroll
    for (int nt = 0; nt < 8; nt++)
        #pragma unroll
        for (int e = 0; e < 4; e++) oacc[nt][e] = 0.f;

    #pragma unroll 1
    for (int chunk = 0; chunk < 8; chunk++) {
        const int s0 = chunk * 128;
        if (chunk) __syncthreads();      // prev MMA2 done reading Vw

        #pragma unroll
        for (int p = 0; p < 8; p++) {
            int sl = psl + p*16;
            uint2 uk = km2[w*16384 + (s0 + sl)*16 + pu2];
            Kw[sl*AT_S + pcw]     = uk.x;
            Kw[sl*AT_S + pcw + 1] = uk.y;
            uint2 uv = vv2[w*16384 + (s0 + sl)*16 + pu2];
            Vw[sl*AT_S + pcw]     = uv.x;
            Vw[sl*AT_S + pcw + 1] = uv.y;
        }
        __syncthreads();

        // ---- MMA1: S'(16x128) per warp, ldmatrix.x4 frags ----
        float sacc[16][4];
        #pragma unroll
        for (int nt = 0; nt < 16; nt++)
            #pragma unroll
            for (int e = 0; e < 4; e++) sacc[nt][e] = 0.f;

        #pragma unroll
        for (int kk = 0; kk < 4; kk++) {
            uint32_t a[4];
            ldsm_x4(a, qbase + (uint32_t)((r0 + l8 + lhi*8)*(AT_S*4) + kk*32 + lcol*16));
            #pragma unroll
            for (int nt2 = 0; nt2 < 8; nt2++) {
                uint32_t b[4];
                ldsm_x4(b, kbase + (uint32_t)((nt2*16 + l8 + lhi*8)*(AT_S*4) + kk*32 + lcol*16));
                uint32_t b02[2] = {b[0], b[2]}, b13[2] = {b[1], b[3]};
                MMA_F16(sacc[2*nt2],     a, b02);
                MMA_F16(sacc[2*nt2 + 1], a, b13);
            }
        }

        // relu + pack: MMA1 c-frags -> MMA2 a-frags (register-resident S)
        uint32_t ap[8][4];
        #pragma unroll
        for (int kk2 = 0; kk2 < 8; kk2++) {
            ap[kk2][0] = pack_half2(fmaxf(sacc[2*kk2][0], 0.f),
                                    fmaxf(sacc[2*kk2][1], 0.f));
            ap[kk2][1] = pack_half2(fmaxf(sacc[2*kk2][2], 0.f),
                                    fmaxf(sacc[2*kk2][3], 0.f));
            ap[kk2][2] = pack_half2(fmaxf(sacc[2*kk2+1][0], 0.f),
                                    fmaxf(sacc[2*kk2+1][1], 0.f));
            ap[kk2][3] = pack_half2(fmaxf(sacc[2*kk2+1][2], 0.f),
                                    fmaxf(sacc[2*kk2+1][3], 0.f));
        }

        // ---- MMA2: O(16x64) += S' V, b via ldmatrix.x4.trans ----
        #pragma unroll
        for (int kk2 = 0; kk2 < 8; kk2++) {
            #pragma unroll
            for (int ntv = 0; ntv < 4; ntv++) {
                uint32_t b[4];
                ldsm_x4_trans(b, vbase + (uint32_t)((kk2*16 + l8 + lhi*8)*(AT_S*4)
                                                    + (ntv*16 + lcol*8)*2));
                uint32_t b01[2] = {b[0], b[1]}, b23[2] = {b[2], b[3]};
                MMA_F16(oacc[2*ntv],     ap[kk2], b01);
                MMA_F16(oacc[2*ntv + 1], ap[kk2], b23);
            }
        }
    }

    __syncthreads();
    // stage O/16384 as fp32 [t][c] (reuses Qw/Kw region)
    #pragma unroll
    for (int nt = 0; nt < 8; nt++) {
        int c = nt*8 + 2*tig;
        Sg[(r0 + gid    )*AT_SG + c    ] = oacc[nt][0] * (1.f/16384.f);
        Sg[(r0 + gid    )*AT_SG + c + 1] = oacc[nt][1] * (1.f/16384.f);
        Sg[(r0 + gid + 8)*AT_SG + c    ] = oacc[nt][2] * (1.f/16384.f);
        Sg[(r0 + gid + 8)*AT_SG + c + 1] = oacc[nt][3] * (1.f/16384.f);
    }
    __syncthreads();

    #pragma unroll
    for (int i = 0; i < 32; i++) {
        int idx = tid + i*256;
        int ch = idx >> 7, tl = idx & 127;
        int t  = t0 + tl;
        out[ch*65536 + (wy*32 + (t>>5))*256 + wx*32 + (t&31)] = Sg[tl*AT_SG + ch];
    }
}

// ---------------------------------------------------------------------------
extern "C" void kernel_launch(void* const* d_in, const int* in_sizes, int n_in,
                              void* d_out, int out_size)
{
    const float* x    = (const float*)d_in[0];
    const float* W    = (const float*)d_in[1];
    const float* bias = (const float*)d_in[2];
    float* out = (float*)d_out;

    cudaFuncSetAttribute(qkv_kernel,  cudaFuncAttributeMaxDynamicSharedMemorySize, QKV_SMEM);
    cudaFuncSetAttribute(mix_kernel,  cudaFuncAttributeMaxDynamicSharedMemorySize, MIX_SMEM);
    cudaFuncSetAttribute(attn_kernel, cudaFuncAttributeMaxDynamicSharedMemorySize, ATTN_SMEM);

    qkv_kernel <<<dim3(512, 2), 256, QKV_SMEM>>>(x, W, bias);
    ar_kernel  <<<1,            256>>>();
    mix_kernel <<<dim3(512, 2), 256, MIX_SMEM>>>();
    attn_kernel<<<512,          256, ATTN_SMEM>>>(out);
}

// round 13
// speedup vs baseline: 2.2617x; 1.2691x over previous
#include <cuda_runtime.h>
#include <cuda_fp16.h>
#include <cstdint>

// Problem constants: x (1,64,256,256), W (192,64), bias (192), 8x8 windows of 32x32.
#define NWIN 64
#define TOK  1024
#define C    64
#define WELEMS (TOK*C)          // 65536 floats per window per tensor

// Scratch (device globals — no allocation allowed)
__device__ uint32_t g_qh  [NWIN*WELEMS/2];      // fp16 half2 [w][t][c/2]
__device__ uint32_t g_kh  [NWIN*WELEMS/2];      // fp16 half2
__device__ uint32_t g_vh  [NWIN*WELEMS/2];      // fp16 half2
__device__ uint32_t g_qmh [NWIN*WELEMS/2];      // fp16 half2, x128 scaled
__device__ uint32_t g_kmh [NWIN*WELEMS/2];      // fp16 half2, x128 scaled
__device__ float    g_part[1024*2*96];          // qkv per-block channel sums
__device__ float    g_ar  [NWIN*NWIN];          // x64 prescaled

// ---------------------------------------------------------------------------
// fp16 helpers
// ---------------------------------------------------------------------------
__device__ __forceinline__ uint32_t pack_half2(float lo, float hi) {
    uint32_t r;
    asm("cvt.rn.f16x2.f32 %0, %1, %2;" : "=r"(r) : "f"(hi), "f"(lo));
    return r;   // d.lo = lo, d.hi = hi
}

#define MMA_F16(d, a, b)                                                      \
    asm volatile(                                                             \
        "mma.sync.aligned.m16n8k16.row.col.f32.f16.f16.f32 "                  \
        "{%0,%1,%2,%3}, {%4,%5,%6,%7}, {%8,%9}, {%0,%1,%2,%3};"               \
        : "+f"((d)[0]), "+f"((d)[1]), "+f"((d)[2]), "+f"((d)[3])              \
        : "r"((a)[0]), "r"((a)[1]), "r"((a)[2]), "r"((a)[3]),                 \
          "r"((b)[0]), "r"((b)[1]))

__device__ __forceinline__ uint32_t smem_u32(const void* p) {
    uint32_t a;
    asm("{ .reg .u64 t; cvta.to.shared.u64 t, %1; cvt.u32.u64 %0, t; }"
        : "=r"(a) : "l"(p));
    return a;
}
__device__ __forceinline__ void ldsm_x4(uint32_t* r, uint32_t addr) {
    asm volatile("ldmatrix.sync.aligned.m8n8.x4.shared.b16 {%0,%1,%2,%3}, [%4];"
        : "=r"(r[0]), "=r"(r[1]), "=r"(r[2]), "=r"(r[3]) : "r"(addr));
}
__device__ __forceinline__ void ldsm_x4_trans(uint32_t* r, uint32_t addr) {
    asm volatile("ldmatrix.sync.aligned.m8n8.x4.trans.shared.b16 {%0,%1,%2,%3}, [%4];"
        : "=r"(r[0]), "=r"(r[1]), "=r"(r[2]), "=r"(r[3]) : "r"(addr));
}
__device__ __forceinline__ void cp_async16(uint32_t dst, const void* src) {
    asm volatile("cp.async.cg.shared.global [%0], [%1], 16;" :: "r"(dst), "l"(src));
}
#define CP_COMMIT() asm volatile("cp.async.commit_group;" ::: "memory")
#define CP_WAIT0()  asm volatile("cp.async.wait_group 0;"  ::: "memory")

// ---------------------------------------------------------------------------
// Kernel 1: qkv = gather(x) @ W^T + bias, split-FP16 (~fp32 accurate).
// X = xh+xl fp16; W prescaled x16 = wh+wl fp16 (lo stays normal).
// acc = Xh*Wh + Xl*Wh + Xh*Wl (fp32);  out = acc/16 + bias.
// grid (512, 2): token-tile of 128 x 96-output half. Warp tile m32 x n48.
// Outputs q/k/v packed fp16; per-block channel sums -> g_part.
// ---------------------------------------------------------------------------
#define QKV_XW 36    // X half2 words/row (32 + 4 pad)
#define QKV_WW 36    // W half2 words/row
#define QKV_SG 100
#define QKV_SMEM ((2*128*QKV_XW + 2*96*QKV_WW + 96)*4)   // 64896 B

__global__ __launch_bounds__(256) void qkv_kernel(const float* __restrict__ x,
                                                  const float* __restrict__ W,
                                                  const float* __restrict__ bias)
{
    extern __shared__ uint32_t smw[];
    uint32_t* Xh = smw;                   // [128][36]
    uint32_t* Xl = Xh + 128*QKV_XW;       // [128][36]
    uint32_t* Wh = Xl + 128*QKV_XW;       // [96][36]
    uint32_t* Wl = Wh + 96*QKV_WW;        // [96][36]
    float*    bs = (float*)(Wl + 96*QKV_WW);   // [96]
    float*    Sg = (float*)smw;           // stage [128][100] (union w/ operands)

    const int tt  = blockIdx.x;
    const int jh  = blockIdx.y;
    const int w   = tt >> 3, seg = tt & 7;
    const int wy  = w >> 3,  wx  = w & 7;
    const int t0  = seg * 128;
    const int tid = threadIdx.x;
    const int warp = tid >> 5, lane = tid & 31;
    const int gid  = lane >> 2, tig = lane & 3;
    const int mwarp = warp >> 1;          // 0..3 -> 32 rows
    const int nwarp = warp & 1;           // 0..1 -> 48 cols

    __half* Xhh = (__half*)Xh;            // stride 72 halves/row
    __half* Xlh = (__half*)Xl;
    __half* Whh = (__half*)Wh;
    __half* Wlh = (__half*)Wl;

    // X split -> fp16 hi/lo (coalesced gmem reads)
    #pragma unroll
    for (int i = 0; i < 32; i++) {
        int idx = tid + i*256;
        int ch = idx >> 7, tl = idx & 127;
        int t  = t0 + tl;
        float v = x[ch*65536 + (wy*32 + (t>>5))*256 + wx*32 + (t&31)];
        __half h = __float2half_rn(v);
        Xhh[tl*72 + ch] = h;
        Xlh[tl*72 + ch] = __float2half_rn(v - __half2float(h));
    }
    // W x16 split -> fp16 hi/lo, layout [j][c]
    #pragma unroll
    for (int i = 0; i < 24; i++) {
        int idx = tid + i*256;
        int ch = idx & 63, jl = idx >> 6;
        float v = W[(jh*96 + jl)*64 + ch] * 16.f;
        __half h = __float2half_rn(v);
        Whh[jl*72 + ch] = h;
        Wlh[jl*72 + ch] = __float2half_rn(v - __half2float(h));
    }
    if (tid < 96) bs[tid] = bias[jh*96 + tid];
    __syncthreads();

    float acc[2][6][4];
    #pragma unroll
    for (int mt = 0; mt < 2; mt++)
        #pragma unroll
        for (int nt = 0; nt < 6; nt++)
            #pragma unroll
            for (int e = 0; e < 4; e++) acc[mt][nt][e] = 0.f;

    #pragma unroll
    for (int kk = 0; kk < 4; kk++) {
        int kw = kk*8;
        uint32_t ah[2][4], al[2][4];
        #pragma unroll
        for (int mt = 0; mt < 2; mt++) {
            int r = mwarp*32 + mt*16 + gid;
            ah[mt][0] = Xh[ r     *QKV_XW + kw + tig];
            ah[mt][1] = Xh[(r + 8)*QKV_XW + kw + tig];
            ah[mt][2] = Xh[ r     *QKV_XW + kw + 4 + tig];
            ah[mt][3] = Xh[(r + 8)*QKV_XW + kw + 4 + tig];
            al[mt][0] = Xl[ r     *QKV_XW + kw + tig];
            al[mt][1] = Xl[(r + 8)*QKV_XW + kw + tig];
            al[mt][2] = Xl[ r     *QKV_XW + kw + 4 + tig];
            al[mt][3] = Xl[(r + 8)*QKV_XW + kw + 4 + tig];
        }
        #pragma unroll
        for (int nt = 0; nt < 6; nt++) {
            int j = nwarp*48 + nt*8 + gid;
            uint32_t bh[2], bl[2];
            bh[0] = Wh[j*QKV_WW + kw + tig];
            bh[1] = Wh[j*QKV_WW + kw + 4 + tig];
            bl[0] = Wl[j*QKV_WW + kw + tig];
            bl[1] = Wl[j*QKV_WW + kw + 4 + tig];
            MMA_F16(acc[0][nt], ah[0], bh);
            MMA_F16(acc[0][nt], al[0], bh);
            MMA_F16(acc[0][nt], ah[0], bl);
            MMA_F16(acc[1][nt], ah[1], bh);
            MMA_F16(acc[1][nt], al[1], bh);
            MMA_F16(acc[1][nt], ah[1], bl);
        }
    }
    __syncthreads();   // operands dead; stage region reuses them (bias survives)

    #pragma unroll
    for (int mt = 0; mt < 2; mt++) {
        int r = mwarp*32 + mt*16 + gid;
        #pragma unroll
        for (int nt = 0; nt < 6; nt++) {
            int j = nwarp*48 + nt*8 + 2*tig;
            Sg[ r     *QKV_SG + j    ] = acc[mt][nt][0]*(1.f/16.f) + bs[j];
            Sg[ r     *QKV_SG + j + 1] = acc[mt][nt][1]*(1.f/16.f) + bs[j+1];
            Sg[(r + 8)*QKV_SG + j    ] = acc[mt][nt][2]*(1.f/16.f) + bs[j];
            Sg[(r + 8)*QKV_SG + j + 1] = acc[mt][nt][3]*(1.f/16.f) + bs[j+1];
        }
    }
    __syncthreads();

    // copy-out: q/k/v as packed fp16
    #pragma unroll
    for (int p = 0; p < 12; p++) {
        int idx = tid + p*256;
        int t  = idx / 24, f4 = idx % 24;
        float4 v = *(float4*)&Sg[t*QKV_SG + f4*4];
        int jg = jh*96 + f4*4;
        uint32_t* dst = (jg < 64) ? g_qh : (jg < 128) ? g_kh : g_vh;
        int jj = jg & 63;
        uint2 u;
        u.x = pack_half2(v.x, v.y);
        u.y = pack_half2(v.z, v.w);
        *(uint2*)&dst[w*32768 + (t0 + t)*32 + (jj >> 1)] = u;
    }

    // per-block channel sums over 128 tokens (deterministic mean reduction)
    if (tid < 96) {
        float s = 0.f;
        #pragma unroll 8
        for (int t = 0; t < 128; t++) s += Sg[t*QKV_SG + tid];
        g_part[(tt*2 + jh)*96 + tid] = s;
    }
}

// ---------------------------------------------------------------------------
// Kernel 2: a_r = relu(q_r @ k_r^T) from qkv partial sums. Output x64
// prescaled (mix packs x2 -> net x128 for attn).
// ---------------------------------------------------------------------------
__global__ void ar_kernel()
{
    __shared__ float qs[NWIN*C], ks[NWIN*C];
    const int tid = threadIdx.x;
    for (int e = tid; e < NWIN*C; e += 256) {
        int w = e >> 6, c = e & 63;
        float sq = 0.f, sk = 0.f;
        #pragma unroll
        for (int seg = 0; seg < 8; seg++) {
            int tt = w*8 + seg;
            sq += g_part[(tt*2 + 0)*96 + c];
            sk += (c < 32) ? g_part[(tt*2 + 0)*96 + 64 + c]
                           : g_part[(tt*2 + 1)*96 + (c - 32)];
        }
        qs[e] = sq; ks[e] = sk;
    }
    __syncthreads();
    for (int e = tid; e < NWIN*NWIN; e += 256) {
        int i = e >> 6, j = e & 63;
        float s = 0.f;
        #pragma unroll
        for (int c = 0; c < 64; c++) s += qs[i*64 + c] * ks[j*64 + c];
        g_ar[e] = fmaxf(s, 0.f) * (1.f/16384.f);   // (1/1024^2) * 64
    }
}

// ---------------------------------------------------------------------------
// Kernel 3: q_m/k_m = a_r @ src, fp16 MMA (A = split-fp16 a_r, B = fp16 q/k).
// grid (512, 2). Warp tile m16 x n64. Output packed fp16 x128 net scale.
// ---------------------------------------------------------------------------
#define MIX_AW 36
#define MIX_BW 68
#define MIX_SW 68
#define MIX_SMEM ((2*64*MIX_AW + 64*MIX_BW)*4)   // 35840 B

__global__ __launch_bounds__(256) void mix_kernel()
{
    extern __shared__ uint32_t smw[];
    uint32_t* Ah = smw;                   // [64][36] half2 (hi)
    uint32_t* Al = Ah + 64*MIX_AW;        // [64][36] half2 (lo)
    uint32_t* Bs = Al + 64*MIX_AW;        // [64][68] half2 [j][pos]
    uint32_t* Sw = smw;                   // fp16 stage [64][68] (union w/ Ah+Al)

    const int tid = threadIdx.x;
    const int warp = tid >> 5, lane = tid & 31;
    const int gid  = lane >> 2, tig = lane & 3;
    const int mwarp = warp >> 1;
    const int nwarp = warp & 1;
    const int l8 = lane & 7, lhi = (lane >> 3) & 1, lcol = lane >> 4;
    const uint2* srch = (const uint2*)(blockIdx.y ? g_kh : g_qh);
    uint32_t*    dst  = blockIdx.y ? g_kmh : g_qmh;
    const int pos0 = blockIdx.x * 128;

    #pragma unroll
    for (int p = 0; p < 8; p++) {
        int idx = tid + p*256;
        int i = idx >> 5, jw = idx & 31;
        float v0 = g_ar[i*64 + jw*2], v1 = g_ar[i*64 + jw*2 + 1];
        float h0 = __half2float(__float2half_rn(v0));
        float h1 = __half2float(__float2half_rn(v1));
        Ah[i*MIX_AW + jw] = pack_half2(v0, v1);
        Al[i*MIX_AW + jw] = pack_half2(v0 - h0, v1 - h1);
    }
    #pragma unroll
    for (int p = 0; p < 8; p++) {
        int idx = tid + p*256;
        int j = idx >> 5, u2 = idx & 31;
        uint2 u = srch[j*16384 + (pos0 >> 2) + u2];
        *(uint2*)&Bs[j*MIX_BW + u2*2] = u;
    }
    __syncthreads();

    float acc[8][4];
    #pragma unroll
    for (int nt = 0; nt < 8; nt++)
        #pragma unroll
        for (int e = 0; e < 4; e++) acc[nt][e] = 0.f;

    const uint32_t bbase = smem_u32(Bs);
    const int r = mwarp*16 + gid;

    #pragma unroll
    for (int kk = 0; kk < 4; kk++) {
        uint32_t ah[4], al[4];
        ah[0] = Ah[ r     *MIX_AW + kk*8 + tig];
        ah[1] = Ah[(r + 8)*MIX_AW + kk*8 + tig];
        ah[2] = Ah[ r     *MIX_AW + kk*8 + 4 + tig];
        ah[3] = Ah[(r + 8)*MIX_AW + kk*8 + 4 + tig];
        al[0] = Al[ r     *MIX_AW + kk*8 + tig];
        al[1] = Al[(r + 8)*MIX_AW + kk*8 + tig];
        al[2] = Al[ r     *MIX_AW + kk*8 + 4 + tig];
        al[3] = Al[(r + 8)*MIX_AW + kk*8 + 4 + tig];
        #pragma unroll
        for (int ntv = 0; ntv < 4; ntv++) {
            int n0 = nwarp*64 + ntv*16;
            uint32_t b[4];
            ldsm_x4_trans(b, bbase + (uint32_t)((kk*16 + l8 + lhi*8)*(MIX_BW*4)
                                                + (n0 + lcol*8)*2));
            uint32_t b01[2] = {b[0], b[1]}, b23[2] = {b[2], b[3]};
            MMA_F16(acc[2*ntv],     ah, b01);
            MMA_F16(acc[2*ntv],     al, b01);
            MMA_F16(acc[2*ntv + 1], ah, b23);
            MMA_F16(acc[2*ntv + 1], al, b23);
        }
    }
    __syncthreads();

    #pragma unroll
    for (int nt = 0; nt < 8; nt++) {
        int wc = nwarp*32 + nt*4 + tig;
        Sw[ r     *MIX_SW + wc] = pack_half2(acc[nt][0]*2.f, acc[nt][1]*2.f);
        Sw[(r + 8)*MIX_SW + wc] = pack_half2(acc[nt][2]*2.f, acc[nt][3]*2.f);
    }
    __syncthreads();

    #pragma unroll
    for (int p = 0; p < 4; p++) {
        int idx = tid + p*256;
        int i = idx >> 4, w4 = idx & 15;
        uint4 v = *(uint4*)&Sw[i*MIX_SW + w4*4];
        ((uint4*)dst)[i*8192 + (pos0 >> 3) + w4] = v;
    }
}

// ---------------------------------------------------------------------------
// Kernel 4 (dominant): O = relu(Qm Km^T) V, fp16 mma, register-resident S,
// cp.async DOUBLE-BUFFERED K/V (1 barrier per chunk, loads hidden under MMA).
// smem: Q[128][36] + K[2][128][36] + V[2][128][36] = 92160 B -> 2 CTAs/SM.
// ---------------------------------------------------------------------------
#define AT_S  36    // Q/K/V word stride (144 B rows: ldsm conflict-free)
#define AT_SG 68    // output stage stride (floats)
#define AT_TILE (128*AT_S*4)        // 18432 B per tile
#define ATTN_SMEM (5*AT_TILE)       // 92160 B

__global__ __launch_bounds__(256, 2) void attn_kernel(float* __restrict__ out)
{
    extern __shared__ uint32_t smw[];
    float* Sg = (float*)smw;             // output stage (reuses Q + K bufs)

    const int bx = blockIdx.x;
    const int w  = bx >> 3, seg = bx & 7;
    const int wy = w >> 3,  wx  = w & 7;
    const int t0 = seg * 128;
    const int tid = threadIdx.x;
    const int warp = tid >> 5, lane = tid & 31;
    const int gid = lane >> 2, tig = lane & 3;
    const int r0 = warp*16;              // warp's m rows
    const int l8 = lane & 7, lhi = (lane >> 3) & 1, lcol = lane >> 4;

    const uint32_t sb = smem_u32(smw);
    const char* qsrc = (const char*)g_qmh + w*131072;
    const char* ksrc = (const char*)g_kmh + w*131072;
    const char* vsrc = (const char*)g_vh  + w*131072;

    // Prologue: cp.async Q tile + chunk-0 K/V into buffer 0 (4 slots each/thr)
    #pragma unroll
    for (int p = 0; p < 4; p++) {
        int slot = tid + p*256;          // 1024 slots = 128 rows x 8 segs
        int row = slot >> 3, sg16 = slot & 7;
        cp_async16(sb +              row*144 + sg16*16, qsrc + (t0 + row)*128 + sg16*16);
        cp_async16(sb +   AT_TILE +  row*144 + sg16*16, ksrc + row*128 + sg16*16);
        cp_async16(sb + 3*AT_TILE +  row*144 + sg16*16, vsrc + row*128 + sg16*16);
    }
    CP_COMMIT();

    float oacc[8][4];
    #pragma unroll
    for (int nt = 0; nt < 8; nt++)
        #pragma unroll
        for (int e = 0; e < 4; e++) oacc[nt][e] = 0.f;

    #pragma unroll 1
    for (int chunk = 0; chunk < 8; chunk++) {
        CP_WAIT0();
        __syncthreads();                 // buf[chunk&1] ready for all warps

        // Issue next chunk's K/V into the other buffer (hidden under MMAs)
        if (chunk < 7) {
            const int sn = (chunk + 1) * 128;
            const uint32_t kb_n = sb + (1 + ((chunk + 1) & 1))*AT_TILE;
            const uint32_t vb_n = sb + (3 + ((chunk + 1) & 1))*AT_TILE;
            #pragma unroll
            for (int p = 0; p < 4; p++) {
                int slot = tid + p*256;
                int row = slot >> 3, sg16 = slot & 7;
                cp_async16(kb_n + row*144 + sg16*16, ksrc + (sn + row)*128 + sg16*16);
                cp_async16(vb_n + row*144 + sg16*16, vsrc + (sn + row)*128 + sg16*16);
            }
            CP_COMMIT();
        }

        const uint32_t kb = sb + (1 + (chunk & 1))*AT_TILE;
        const uint32_t vb = sb + (3 + (chunk & 1))*AT_TILE;

        // ---- MMA1: S'(16x128) per warp ----
        float sacc[16][4];
        #pragma unroll
        for (int nt = 0; nt < 16; nt++)
            #pragma unroll
            for (int e = 0; e < 4; e++) sacc[nt][e] = 0.f;

        #pragma unroll
        for (int kk = 0; kk < 4; kk++) {
            uint32_t a[4];
            ldsm_x4(a, sb + (uint32_t)((r0 + l8 + lhi*8)*144 + kk*32 + lcol*16));
            #pragma unroll
            for (int nt2 = 0; nt2 < 8; nt2++) {
                uint32_t b[4];
                ldsm_x4(b, kb + (uint32_t)((nt2*16 + l8 + lhi*8)*144 + kk*32 + lcol*16));
                uint32_t b02[2] = {b[0], b[2]}, b13[2] = {b[1], b[3]};
                MMA_F16(sacc[2*nt2],     a, b02);
                MMA_F16(sacc[2*nt2 + 1], a, b13);
            }
        }

        // relu + pack: MMA1 c-frags -> MMA2 a-frags (register-resident S)
        uint32_t ap[8][4];
        #pragma unroll
        for (int kk2 = 0; kk2 < 8; kk2++) {
            ap[kk2][0] = pack_half2(fmaxf(sacc[2*kk2][0], 0.f),
                                    fmaxf(sacc[2*kk2][1], 0.f));
            ap[kk2][1] = pack_half2(fmaxf(sacc[2*kk2][2], 0.f),
                                    fmaxf(sacc[2*kk2][3], 0.f));
            ap[kk2][2] = pack_half2(fmaxf(sacc[2*kk2+1][0], 0.f),
                                    fmaxf(sacc[2*kk2+1][1], 0.f));
            ap[kk2][3] = pack_half2(fmaxf(sacc[2*kk2+1][2], 0.f),
                                    fmaxf(sacc[2*kk2+1][3], 0.f));
        }

        // ---- MMA2: O(16x64) += S' V ----
        #pragma unroll
        for (int kk2 = 0; kk2 < 8; kk2++) {
            #pragma unroll
            for (int ntv = 0; ntv < 4; ntv++) {
                uint32_t b[4];
                ldsm_x4_trans(b, vb + (uint32_t)((kk2*16 + l8 + lhi*8)*144
                                                 + (ntv*16 + lcol*8)*2));
                uint32_t b01[2] = {b[0], b[1]}, b23[2] = {b[2], b[3]};
                MMA_F16(oacc[2*ntv],     ap[kk2], b01);
                MMA_F16(oacc[2*ntv + 1], ap[kk2], b23);
            }
        }
    }

    __syncthreads();
    // stage O/16384 as fp32 [t][c] (reuses Q + K-buffer region: 34.8KB < 55.3KB)
    #pragma unroll
    for (int nt = 0; nt < 8; nt++) {
        int c = nt*8 + 2*tig;
        Sg[(r0 + gid    )*AT_SG + c    ] = oacc[nt][0] * (1.f/16384.f);
        Sg[(r0 + gid    )*AT_SG + c + 1] = oacc[nt][1] * (1.f/16384.f);
        Sg[(r0 + gid + 8)*AT_SG + c    ] = oacc[nt][2] * (1.f/16384.f);
        Sg[(r0 + gid + 8)*AT_SG + c + 1] = oacc[nt][3] * (1.f/16384.f);
    }
    __syncthreads();

    #pragma unroll
    for (int i = 0; i < 32; i++) {
        int idx = tid + i*256;
        int ch = idx >> 7, tl = idx & 127;
        int t  = t0 + tl;
        out[ch*65536 + (wy*32 + (t>>5))*256 + wx*32 + (t&31)] = Sg[tl*AT_SG + ch];
    }
}

// ---------------------------------------------------------------------------
extern "C" void kernel_launch(void* const* d_in, const int* in_sizes, int n_in,
                              void* d_out, int out_size)
{
    const float* x    = (const float*)d_in[0];
    const float* W    = (const float*)d_in[1];
    const float* bias = (const float*)d_in[2];
    float* out = (float*)d_out;

    cudaFuncSetAttribute(qkv_kernel,  cudaFuncAttributeMaxDynamicSharedMemorySize, QKV_SMEM);
    cudaFuncSetAttribute(mix_kernel,  cudaFuncAttributeMaxDynamicSharedMemorySize, MIX_SMEM);
    cudaFuncSetAttribute(attn_kernel, cudaFuncAttributeMaxDynamicSharedMemorySize, ATTN_SMEM);

    qkv_kernel <<<dim3(512, 2), 256, QKV_SMEM>>>(x, W, bias);
    ar_kernel  <<<1,            256>>>();
    mix_kernel <<<dim3(512, 2), 256, MIX_SMEM>>>();
    attn_kernel<<<512,          256, ATTN_SMEM>>>(out);
}

// round 14
// speedup vs baseline: 2.3791x; 1.0519x over previous
#include <cuda_runtime.h>
#include <cuda_fp16.h>
#include <cstdint>

// Problem constants: x (1,64,256,256), W (192,64), bias (192), 8x8 windows of 32x32.
#define NWIN 64
#define TOK  1024
#define C    64
#define WELEMS (TOK*C)          // 65536 floats per window per tensor

// Scratch (device globals — no allocation allowed)
__device__ uint32_t g_qh  [NWIN*WELEMS/2];      // fp16 half2 [w][t][c/2]
__device__ uint32_t g_kh  [NWIN*WELEMS/2];      // fp16 half2
__device__ uint32_t g_vh  [NWIN*WELEMS/2];      // fp16 half2
__device__ uint32_t g_qmh [NWIN*WELEMS/2];      // fp16 half2, x128 scaled
__device__ uint32_t g_kmh [NWIN*WELEMS/2];      // fp16 half2, x128 scaled
__device__ float    g_part[1024*2*96];          // qkv per-block channel sums
__device__ float    g_ar  [NWIN*NWIN];          // x64 prescaled

// ---------------------------------------------------------------------------
// fp16 helpers
// ---------------------------------------------------------------------------
__device__ __forceinline__ uint32_t pack_half2(float lo, float hi) {
    uint32_t r;
    asm("cvt.rn.f16x2.f32 %0, %1, %2;" : "=r"(r) : "f"(hi), "f"(lo));
    return r;   // d.lo = lo, d.hi = hi
}

#define MMA_F16(d, a, b)                                                      \
    asm volatile(                                                             \
        "mma.sync.aligned.m16n8k16.row.col.f32.f16.f16.f32 "                  \
        "{%0,%1,%2,%3}, {%4,%5,%6,%7}, {%8,%9}, {%0,%1,%2,%3};"               \
        : "+f"((d)[0]), "+f"((d)[1]), "+f"((d)[2]), "+f"((d)[3])              \
        : "r"((a)[0]), "r"((a)[1]), "r"((a)[2]), "r"((a)[3]),                 \
          "r"((b)[0]), "r"((b)[1]))

__device__ __forceinline__ uint32_t smem_u32(const void* p) {
    uint32_t a;
    asm("{ .reg .u64 t; cvta.to.shared.u64 t, %1; cvt.u32.u64 %0, t; }"
        : "=r"(a) : "l"(p));
    return a;
}
__device__ __forceinline__ void ldsm_x4(uint32_t* r, uint32_t addr) {
    asm volatile("ldmatrix.sync.aligned.m8n8.x4.shared.b16 {%0,%1,%2,%3}, [%4];"
        : "=r"(r[0]), "=r"(r[1]), "=r"(r[2]), "=r"(r[3]) : "r"(addr));
}
__device__ __forceinline__ void ldsm_x4_trans(uint32_t* r, uint32_t addr) {
    asm volatile("ldmatrix.sync.aligned.m8n8.x4.trans.shared.b16 {%0,%1,%2,%3}, [%4];"
        : "=r"(r[0]), "=r"(r[1]), "=r"(r[2]), "=r"(r[3]) : "r"(addr));
}
__device__ __forceinline__ void cp_async16(uint32_t dst, const void* src) {
    asm volatile("cp.async.cg.shared.global [%0], [%1], 16;" :: "r"(dst), "l"(src));
}
#define CP_COMMIT() asm volatile("cp.async.commit_group;" ::: "memory")
#define CP_WAIT0()  asm volatile("cp.async.wait_group 0;"  ::: "memory")

// ---------------------------------------------------------------------------
// Kernel 1: qkv = gather(x) @ W^T + bias, split-FP16 (~fp32 accurate).
// X = xh+xl fp16; W prescaled x16 = wh+wl fp16. out = acc/16 + bias.
// grid (512, 2). Outputs q/k/v packed fp16; channel partial sums -> g_part.
// ---------------------------------------------------------------------------
#define QKV_XW 36
#define QKV_WW 36
#define QKV_SG 100
#define QKV_SMEM ((2*128*QKV_XW + 2*96*QKV_WW + 96)*4 + 192*4)   // 65664 B

__global__ __launch_bounds__(256) void qkv_kernel(const float* __restrict__ x,
                                                  const float* __restrict__ W,
                                                  const float* __restrict__ bias)
{
    extern __shared__ uint32_t smw[];
    uint32_t* Xh = smw;                   // [128][36]
    uint32_t* Xl = Xh + 128*QKV_XW;       // [128][36]
    uint32_t* Wh = Xl + 128*QKV_XW;       // [96][36]
    uint32_t* Wl = Wh + 96*QKV_WW;        // [96][36]
    float*    bs = (float*)(Wl + 96*QKV_WW);   // [96]
    float*    red = bs + 96;              // [192]
    float*    Sg = (float*)smw;           // stage [128][100] (union w/ operands)

    const int tt  = blockIdx.x;
    const int jh  = blockIdx.y;
    const int w   = tt >> 3, seg = tt & 7;
    const int wy  = w >> 3,  wx  = w & 7;
    const int t0  = seg * 128;
    const int tid = threadIdx.x;
    const int warp = tid >> 5, lane = tid & 31;
    const int gid  = lane >> 2, tig = lane & 3;
    const int mwarp = warp >> 1;          // 0..3 -> 32 rows
    const int nwarp = warp & 1;           // 0..1 -> 48 cols

    __half* Xhh = (__half*)Xh;            // stride 72 halves/row
    __half* Xlh = (__half*)Xl;
    __half* Whh = (__half*)Wh;
    __half* Wlh = (__half*)Wl;

    #pragma unroll
    for (int i = 0; i < 32; i++) {
        int idx = tid + i*256;
        int ch = idx >> 7, tl = idx & 127;
        int t  = t0 + tl;
        float v = x[ch*65536 + (wy*32 + (t>>5))*256 + wx*32 + (t&31)];
        __half h = __float2half_rn(v);
        Xhh[tl*72 + ch] = h;
        Xlh[tl*72 + ch] = __float2half_rn(v - __half2float(h));
    }
    #pragma unroll
    for (int i = 0; i < 24; i++) {
        int idx = tid + i*256;
        int ch = idx & 63, jl = idx >> 6;
        float v = W[(jh*96 + jl)*64 + ch] * 16.f;
        __half h = __float2half_rn(v);
        Whh[jl*72 + ch] = h;
        Wlh[jl*72 + ch] = __float2half_rn(v - __half2float(h));
    }
    if (tid < 96) bs[tid] = bias[jh*96 + tid];
    __syncthreads();

    float acc[2][6][4];
    #pragma unroll
    for (int mt = 0; mt < 2; mt++)
        #pragma unroll
        for (int nt = 0; nt < 6; nt++)
            #pragma unroll
            for (int e = 0; e < 4; e++) acc[mt][nt][e] = 0.f;

    #pragma unroll
    for (int kk = 0; kk < 4; kk++) {
        int kw = kk*8;
        uint32_t ah[2][4], al[2][4];
        #pragma unroll
        for (int mt = 0; mt < 2; mt++) {
            int r = mwarp*32 + mt*16 + gid;
            ah[mt][0] = Xh[ r     *QKV_XW + kw + tig];
            ah[mt][1] = Xh[(r + 8)*QKV_XW + kw + tig];
            ah[mt][2] = Xh[ r     *QKV_XW + kw + 4 + tig];
            ah[mt][3] = Xh[(r + 8)*QKV_XW + kw + 4 + tig];
            al[mt][0] = Xl[ r     *QKV_XW + kw + tig];
            al[mt][1] = Xl[(r + 8)*QKV_XW + kw + tig];
            al[mt][2] = Xl[ r     *QKV_XW + kw + 4 + tig];
            al[mt][3] = Xl[(r + 8)*QKV_XW + kw + 4 + tig];
        }
        #pragma unroll
        for (int nt = 0; nt < 6; nt++) {
            int j = nwarp*48 + nt*8 + gid;
            uint32_t bh[2], bl[2];
            bh[0] = Wh[j*QKV_WW + kw + tig];
            bh[1] = Wh[j*QKV_WW + kw + 4 + tig];
            bl[0] = Wl[j*QKV_WW + kw + tig];
            bl[1] = Wl[j*QKV_WW + kw + 4 + tig];
            MMA_F16(acc[0][nt], ah[0], bh);
            MMA_F16(acc[0][nt], al[0], bh);
            MMA_F16(acc[0][nt], ah[0], bl);
            MMA_F16(acc[1][nt], ah[1], bh);
            MMA_F16(acc[1][nt], al[1], bh);
            MMA_F16(acc[1][nt], ah[1], bl);
        }
    }
    __syncthreads();   // operands dead; stage region reuses them (bias/red survive)

    #pragma unroll
    for (int mt = 0; mt < 2; mt++) {
        int r = mwarp*32 + mt*16 + gid;
        #pragma unroll
        for (int nt = 0; nt < 6; nt++) {
            int j = nwarp*48 + nt*8 + 2*tig;
            Sg[ r     *QKV_SG + j    ] = acc[mt][nt][0]*(1.f/16.f) + bs[j];
            Sg[ r     *QKV_SG + j + 1] = acc[mt][nt][1]*(1.f/16.f) + bs[j+1];
            Sg[(r + 8)*QKV_SG + j    ] = acc[mt][nt][2]*(1.f/16.f) + bs[j];
            Sg[(r + 8)*QKV_SG + j + 1] = acc[mt][nt][3]*(1.f/16.f) + bs[j+1];
        }
    }
    __syncthreads();

    // copy-out: q/k/v as packed fp16
    #pragma unroll
    for (int p = 0; p < 12; p++) {
        int idx = tid + p*256;
        int t  = idx / 24, f4 = idx % 24;
        float4 v = *(float4*)&Sg[t*QKV_SG + f4*4];
        int jg = jh*96 + f4*4;
        uint32_t* dst = (jg < 64) ? g_qh : (jg < 128) ? g_kh : g_vh;
        int jj = jg & 63;
        uint2 u;
        u.x = pack_half2(v.x, v.y);
        u.y = pack_half2(v.z, v.w);
        *(uint2*)&dst[w*32768 + (t0 + t)*32 + (jj >> 1)] = u;
    }

    // per-block channel sums (2-phase parallel reduction, deterministic)
    if (tid < 192) {
        int half = tid / 96, col = tid - half*96;
        float s = 0.f;
        #pragma unroll 8
        for (int t = half*64; t < half*64 + 64; t++) s += Sg[t*QKV_SG + col];
        red[tid] = s;
    }
    __syncthreads();
    if (tid < 96)
        g_part[(tt*2 + jh)*96 + tid] = red[tid] + red[tid + 96];
}

// ---------------------------------------------------------------------------
// Kernel 2: a_r = relu(q_r @ k_r^T) from qkv partial sums. Output x64
// prescaled (mix packs x2 -> net x128 for attn).
// ---------------------------------------------------------------------------
__global__ void ar_kernel()
{
    __shared__ float qs[NWIN*C], ks[NWIN*C];
    const int tid = threadIdx.x;
    for (int e = tid; e < NWIN*C; e += 256) {
        int w = e >> 6, c = e & 63;
        float sq = 0.f, sk = 0.f;
        #pragma unroll
        for (int seg = 0; seg < 8; seg++) {
            int tt = w*8 + seg;
            sq += g_part[(tt*2 + 0)*96 + c];
            sk += (c < 32) ? g_part[(tt*2 + 0)*96 + 64 + c]
                           : g_part[(tt*2 + 1)*96 + (c - 32)];
        }
        qs[e] = sq; ks[e] = sk;
    }
    __syncthreads();
    for (int e = tid; e < NWIN*NWIN; e += 256) {
        int i = e >> 6, j = e & 63;
        float s = 0.f;
        #pragma unroll
        for (int c = 0; c < 64; c++) s += qs[i*64 + c] * ks[j*64 + c];
        g_ar[e] = fmaxf(s, 0.f) * (1.f/16384.f);   // (1/1024^2) * 64
    }
}

// ---------------------------------------------------------------------------
// Kernel 3: q_m/k_m = a_r @ src, fp16 MMA (A = split-fp16 a_r, B = fp16 q/k).
// grid (512, 2). Warp tile m16 x n64. Output packed fp16 x128 net scale.
// ---------------------------------------------------------------------------
#define MIX_AW 36
#define MIX_BW 68
#define MIX_SW 68
#define MIX_SMEM ((2*64*MIX_AW + 64*MIX_BW)*4)   // 35840 B

__global__ __launch_bounds__(256) void mix_kernel()
{
    extern __shared__ uint32_t smw[];
    uint32_t* Ah = smw;                   // [64][36] half2 (hi)
    uint32_t* Al = Ah + 64*MIX_AW;        // [64][36] half2 (lo)
    uint32_t* Bs = Al + 64*MIX_AW;        // [64][68] half2 [j][pos]
    uint32_t* Sw = smw;                   // fp16 stage [64][68] (union w/ Ah+Al)

    const int tid = threadIdx.x;
    const int warp = tid >> 5, lane = tid & 31;
    const int gid  = lane >> 2, tig = lane & 3;
    const int mwarp = warp >> 1;
    const int nwarp = warp & 1;
    const int l8 = lane & 7, lhi = (lane >> 3) & 1, lcol = lane >> 4;
    const uint2* srch = (const uint2*)(blockIdx.y ? g_kh : g_qh);
    uint32_t*    dst  = blockIdx.y ? g_kmh : g_qmh;
    const int pos0 = blockIdx.x * 128;

    #pragma unroll
    for (int p = 0; p < 8; p++) {
        int idx = tid + p*256;
        int i = idx >> 5, jw = idx & 31;
        float v0 = g_ar[i*64 + jw*2], v1 = g_ar[i*64 + jw*2 + 1];
        float h0 = __half2float(__float2half_rn(v0));
        float h1 = __half2float(__float2half_rn(v1));
        Ah[i*MIX_AW + jw] = pack_half2(v0, v1);
        Al[i*MIX_AW + jw] = pack_half2(v0 - h0, v1 - h1);
    }
    #pragma unroll
    for (int p = 0; p < 8; p++) {
        int idx = tid + p*256;
        int j = idx >> 5, u2 = idx & 31;
        uint2 u = srch[j*16384 + (pos0 >> 2) + u2];
        *(uint2*)&Bs[j*MIX_BW + u2*2] = u;
    }
    __syncthreads();

    float acc[8][4];
    #pragma unroll
    for (int nt = 0; nt < 8; nt++)
        #pragma unroll
        for (int e = 0; e < 4; e++) acc[nt][e] = 0.f;

    const uint32_t bbase = smem_u32(Bs);
    const int r = mwarp*16 + gid;

    #pragma unroll
    for (int kk = 0; kk < 4; kk++) {
        uint32_t ah[4], al[4];
        ah[0] = Ah[ r     *MIX_AW + kk*8 + tig];
        ah[1] = Ah[(r + 8)*MIX_AW + kk*8 + tig];
        ah[2] = Ah[ r     *MIX_AW + kk*8 + 4 + tig];
        ah[3] = Ah[(r + 8)*MIX_AW + kk*8 + 4 + tig];
        al[0] = Al[ r     *MIX_AW + kk*8 + tig];
        al[1] = Al[(r + 8)*MIX_AW + kk*8 + tig];
        al[2] = Al[ r     *MIX_AW + kk*8 + 4 + tig];
        al[3] = Al[(r + 8)*MIX_AW + kk*8 + 4 + tig];
        #pragma unroll
        for (int ntv = 0; ntv < 4; ntv++) {
            int n0 = nwarp*64 + ntv*16;
            uint32_t b[4];
            ldsm_x4_trans(b, bbase + (uint32_t)((kk*16 + l8 + lhi*8)*(MIX_BW*4)
                                                + (n0 + lcol*8)*2));
            uint32_t b01[2] = {b[0], b[1]}, b23[2] = {b[2], b[3]};
            MMA_F16(acc[2*ntv],     ah, b01);
            MMA_F16(acc[2*ntv],     al, b01);
            MMA_F16(acc[2*ntv + 1], ah, b23);
            MMA_F16(acc[2*ntv + 1], al, b23);
        }
    }
    __syncthreads();

    #pragma unroll
    for (int nt = 0; nt < 8; nt++) {
        int wc = nwarp*32 + nt*4 + tig;
        Sw[ r     *MIX_SW + wc] = pack_half2(acc[nt][0]*2.f, acc[nt][1]*2.f);
        Sw[(r + 8)*MIX_SW + wc] = pack_half2(acc[nt][2]*2.f, acc[nt][3]*2.f);
    }
    __syncthreads();

    #pragma unroll
    for (int p = 0; p < 4; p++) {
        int idx = tid + p*256;
        int i = idx >> 4, w4 = idx & 15;
        uint4 v = *(uint4*)&Sw[i*MIX_SW + w4*4];
        ((uint4*)dst)[i*8192 + (pos0 >> 3) + w4] = v;
    }
}

// ---------------------------------------------------------------------------
// Kernel 4 (dominant): O = relu(Qm Km^T) V, fp16 mma, register-resident S.
// NEW SHAPE: 128 threads / 4 warps, each warp owns m32 (two m16 tiles done
// sequentially in MMA1; V fragments shared across both tiles in MMA2) ->
// 104 ldsm per 256 MMAs (2.6x better MMA/LDSM than R13's 8-warp shape).
// cp.async double-buffered K/V, 1 barrier per chunk. 92 KB smem, 2 CTAs/SM.
// ---------------------------------------------------------------------------
#define AT_S  36    // Q/K/V word stride (144 B rows: ldsm conflict-free)
#define AT_SG 68    // output stage stride (floats)
#define AT_TILE (128*AT_S*4)        // 18432 B per tile
#define ATTN_SMEM (5*AT_TILE)       // 92160 B

__global__ __launch_bounds__(128, 2) void attn_kernel(float* __restrict__ out)
{
    extern __shared__ uint32_t smw[];
    float* Sg = (float*)smw;             // output stage (reuses Q + K bufs)

    const int bx = blockIdx.x;
    const int w  = bx >> 3, seg = bx & 7;
    const int wy = w >> 3,  wx  = w & 7;
    const int t0 = seg * 128;
    const int tid = threadIdx.x;
    const int warp = tid >> 5, lane = tid & 31;
    const int gid = lane >> 2, tig = lane & 3;
    const int l8 = lane & 7, lhi = (lane >> 3) & 1, lcol = lane >> 4;

    const uint32_t sb = smem_u32(smw);
    const char* qsrc = (const char*)g_qmh + w*131072;
    const char* ksrc = (const char*)g_kmh + w*131072;
    const char* vsrc = (const char*)g_vh  + w*131072;

    // Prologue: cp.async Q tile + chunk-0 K/V into buffer 0 (8 slots each/thr)
    #pragma unroll
    for (int p = 0; p < 8; p++) {
        int slot = tid + p*128;          // 1024 slots = 128 rows x 8 segs
        int row = slot >> 3, sg16 = slot & 7;
        cp_async16(sb +             row*144 + sg16*16, qsrc + (t0 + row)*128 + sg16*16);
        cp_async16(sb +   AT_TILE + row*144 + sg16*16, ksrc + row*128 + sg16*16);
        cp_async16(sb + 3*AT_TILE + row*144 + sg16*16, vsrc + row*128 + sg16*16);
    }
    CP_COMMIT();

    float oacc[2][8][4];
    #pragma unroll
    for (int mt = 0; mt < 2; mt++)
        #pragma unroll
        for (int nt = 0; nt < 8; nt++)
            #pragma unroll
            for (int e = 0; e < 4; e++) oacc[mt][nt][e] = 0.f;

    #pragma unroll 1
    for (int chunk = 0; chunk < 8; chunk++) {
        CP_WAIT0();
        __syncthreads();                 // buf[chunk&1] ready for all warps

        // Issue next chunk's K/V into the other buffer (hidden under MMAs)
        if (chunk < 7) {
            const int sn = (chunk + 1) * 128;
            const uint32_t kb_n = sb + (1 + ((chunk + 1) & 1))*AT_TILE;
            const uint32_t vb_n = sb + (3 + ((chunk + 1) & 1))*AT_TILE;
            #pragma unroll
            for (int p = 0; p < 8; p++) {
                int slot = tid + p*128;
                int row = slot >> 3, sg16 = slot & 7;
                cp_async16(kb_n + row*144 + sg16*16, ksrc + (sn + row)*128 + sg16*16);
                cp_async16(vb_n + row*144 + sg16*16, vsrc + (sn + row)*128 + sg16*16);
            }
            CP_COMMIT();
        }

        const uint32_t kb = sb + (1 + (chunk & 1))*AT_TILE;
        const uint32_t vb = sb + (3 + (chunk & 1))*AT_TILE;

        // ---- MMA1: two sequential m16 tiles per warp; relu-pack each ----
        uint32_t ap[2][8][4];
        #pragma unroll
        for (int mt = 0; mt < 2; mt++) {
            const int r0w = warp*32 + mt*16;
            float sacc[16][4];
            #pragma unroll
            for (int nt = 0; nt < 16; nt++)
                #pragma unroll
                for (int e = 0; e < 4; e++) sacc[nt][e] = 0.f;

            #pragma unroll
            for (int kk = 0; kk < 4; kk++) {
                uint32_t a[4];
                ldsm_x4(a, sb + (uint32_t)((r0w + l8 + lhi*8)*144 + kk*32 + lcol*16));
                #pragma unroll
                for (int nt2 = 0; nt2 < 8; nt2++) {
                    uint32_t b[4];
                    ldsm_x4(b, kb + (uint32_t)((nt2*16 + l8 + lhi*8)*144 + kk*32 + lcol*16));
                    uint32_t b02[2] = {b[0], b[2]}, b13[2] = {b[1], b[3]};
                    MMA_F16(sacc[2*nt2],     a, b02);
                    MMA_F16(sacc[2*nt2 + 1], a, b13);
                }
            }
            #pragma unroll
            for (int kk2 = 0; kk2 < 8; kk2++) {
                ap[mt][kk2][0] = pack_half2(fmaxf(sacc[2*kk2][0], 0.f),
                                            fmaxf(sacc[2*kk2][1], 0.f));
                ap[mt][kk2][1] = pack_half2(fmaxf(sacc[2*kk2][2], 0.f),
                                            fmaxf(sacc[2*kk2][3], 0.f));
                ap[mt][kk2][2] = pack_half2(fmaxf(sacc[2*kk2+1][0], 0.f),
                                            fmaxf(sacc[2*kk2+1][1], 0.f));
                ap[mt][kk2][3] = pack_half2(fmaxf(sacc[2*kk2+1][2], 0.f),
                                            fmaxf(sacc[2*kk2+1][3], 0.f));
            }
        }

        // ---- MMA2: O(32x64) += S' V, V fragments shared across both m-tiles
        #pragma unroll
        for (int kk2 = 0; kk2 < 8; kk2++) {
            #pragma unroll
            for (int ntv = 0; ntv < 4; ntv++) {
                uint32_t b[4];
                ldsm_x4_trans(b, vb + (uint32_t)((kk2*16 + l8 + lhi*8)*144
                                                 + (ntv*16 + lcol*8)*2));
                uint32_t b01[2] = {b[0], b[1]}, b23[2] = {b[2], b[3]};
                MMA_F16(oacc[0][2*ntv],     ap[0][kk2], b01);
                MMA_F16(oacc[0][2*ntv + 1], ap[0][kk2], b23);
                MMA_F16(oacc[1][2*ntv],     ap[1][kk2], b01);
                MMA_F16(oacc[1][2*ntv + 1], ap[1][kk2], b23);
            }
        }
    }

    __syncthreads();
    // stage O/16384 as fp32 [t][c] (reuses Q + K-buffer region: 34.8KB)
    #pragma unroll
    for (int mt = 0; mt < 2; mt++) {
        const int r0w = warp*32 + mt*16;
        #pragma unroll
        for (int nt = 0; nt < 8; nt++) {
            int c = nt*8 + 2*tig;
            Sg[(r0w + gid    )*AT_SG + c    ] = oacc[mt][nt][0] * (1.f/16384.f);
            Sg[(r0w + gid    )*AT_SG + c + 1] = oacc[mt][nt][1] * (1.f/16384.f);
            Sg[(r0w + gid + 8)*AT_SG + c    ] = oacc[mt][nt][2] * (1.f/16384.f);
            Sg[(r0w + gid + 8)*AT_SG + c + 1] = oacc[mt][nt][3] * (1.f/16384.f);
        }
    }
    __syncthreads();

    #pragma unroll
    for (int i = 0; i < 64; i++) {
        int idx = tid + i*128;
        int ch = idx >> 7, tl = idx & 127;
        int t  = t0 + tl;
        out[ch*65536 + (wy*32 + (t>>5))*256 + wx*32 + (t&31)] = Sg[tl*AT_SG + ch];
    }
}

// ---------------------------------------------------------------------------
extern "C" void kernel_launch(void* const* d_in, const int* in_sizes, int n_in,
                              void* d_out, int out_size)
{
    const float* x    = (const float*)d_in[0];
    const float* W    = (const float*)d_in[1];
    const float* bias = (const float*)d_in[2];
    float* out = (float*)d_out;

    cudaFuncSetAttribute(qkv_kernel,  cudaFuncAttributeMaxDynamicSharedMemorySize, QKV_SMEM);
    cudaFuncSetAttribute(mix_kernel,  cudaFuncAttributeMaxDynamicSharedMemorySize, MIX_SMEM);
    cudaFuncSetAttribute(attn_kernel, cudaFuncAttributeMaxDynamicSharedMemorySize, ATTN_SMEM);

    qkv_kernel <<<dim3(512, 2), 256, QKV_SMEM>>>(x, W, bias);
    ar_kernel  <<<1,            256>>>();
    mix_kernel <<<dim3(512, 2), 256, MIX_SMEM>>>();
    attn_kernel<<<512,          128, ATTN_SMEM>>>(out);
}